// round 1
// baseline (speedup 1.0000x reference)
#include <cuda_runtime.h>

// CARAFE3d: B=1, C=64, D=H=W=32, c_mid=64, s=2, k=3, out_ch=32
// fine grid 64^3, encode channels 216 = 8*27.

#define N3 32768      // 32^3 coarse voxels
#define NF 262144     // 64^3 fine voxels

__device__ float g_w1[64 * N3];          // compressed features [c_mid][32^3]
__device__ float g_w2[216 * N3];         // encode output       [216][32^3]
__device__ float g_wt[64 * 27 * 216];    // transposed encode weights [c][t][o]

typedef unsigned long long u64;

__device__ __forceinline__ u64 pk2(float lo, float hi) {
    u64 r; asm("mov.b64 %0, {%1, %2};" : "=l"(r) : "f"(lo), "f"(hi)); return r;
}
__device__ __forceinline__ void upk2(u64 v, float& lo, float& hi) {
    asm("mov.b64 {%0, %1}, %2;" : "=f"(lo), "=f"(hi) : "l"(v));
}
__device__ __forceinline__ u64 ffma2(u64 a, u64 b, u64 c) {
    u64 d; asm("fma.rn.f32x2 %0, %1, %2, %3;" : "=l"(d) : "l"(a), "l"(b), "l"(c));
    return d;
}

// ---------------------------------------------------------------------------
// Kernel 1: 1x1x1 compress conv.  g_w1[cm][v] = sum_c Wc[cm][c]*x[c][v] + b[cm]
// ---------------------------------------------------------------------------
__global__ __launch_bounds__(256) void k_compress(const float* __restrict__ x,
                                                  const float* __restrict__ Wc,
                                                  const float* __restrict__ bc) {
    __shared__ __align__(16) float Ws[64 * 64];   // [c][cm]
    __shared__ float bs[64];
    int tid = threadIdx.x;
    for (int i = tid; i < 4096; i += 256) {
        int c = i >> 6, cm = i & 63;
        Ws[i] = Wc[cm * 64 + c];
    }
    if (tid < 64) bs[tid] = bc[tid];
    __syncthreads();

    int v = blockIdx.x * 256 + tid;
    const u64* ws64 = (const u64*)Ws;
    u64 acc[32];
#pragma unroll
    for (int p = 0; p < 32; ++p) acc[p] = pk2(bs[2 * p], bs[2 * p + 1]);

#pragma unroll 2
    for (int c = 0; c < 64; ++c) {
        float xv = x[c * N3 + v];
        u64 xd = pk2(xv, xv);
#pragma unroll
        for (int p = 0; p < 32; ++p) acc[p] = ffma2(xd, ws64[c * 32 + p], acc[p]);
    }
#pragma unroll
    for (int p = 0; p < 32; ++p) {
        float a, b; upk2(acc[p], a, b);
        g_w1[(2 * p) * N3 + v]     = a;
        g_w1[(2 * p + 1) * N3 + v] = b;
    }
}

// ---------------------------------------------------------------------------
// Kernel 1b: transpose encode weights [o][c][t] -> [c][t][o] (one-time cheap)
// ---------------------------------------------------------------------------
__global__ __launch_bounds__(256) void k_wtrans(const float* __restrict__ We) {
    int id = blockIdx.x * 256 + threadIdx.x;   // id = c*5832 + t*216 + o
    int c = id / 5832;
    int r = id - c * 5832;
    int t = r / 216;
    int o = r - t * 216;
    g_wt[id] = We[o * 1728 + c * 27 + t];
}

// ---------------------------------------------------------------------------
// Kernel 2: 3x3x3 encode conv (zero pad).  THE hot kernel (12.2 GMAC).
// Block = one (d,h) row (32 w), all 216 output channels, loop c one at a time.
// Thread: wq = tid&3 -> 8 consecutive w; op = tid>>2 -> channel PAIRS
// (2op,2op+1) and (128+2op,129+2op) for op<44.  FFMA2 over channel pairs:
// weight pair = one LDS.64 from [t][o] smem, x scalar dup'd once, reused 8x.
// ---------------------------------------------------------------------------
__global__ __launch_bounds__(256) void k_encode(const float* __restrict__ be) {
    __shared__ float xs[306];                  // [kd*3+kh][34], zero padded
    __shared__ __align__(16) float wsm[5832];  // [t][o] for current channel c
    int tid = threadIdx.x;
    int h = blockIdx.x, d = blockIdx.y;
    int wq = tid & 3;
    int op = tid >> 2;            // 0..63
    int w0 = wq * 8;
    bool has2 = (op < 44);

    u64 acc[2][8];
    {
        u64 b0 = pk2(be[2 * op], be[2 * op + 1]);
        u64 b1 = has2 ? pk2(be[128 + 2 * op], be[129 + 2 * op]) : 0ull;
#pragma unroll
        for (int wi = 0; wi < 8; ++wi) { acc[0][wi] = b0; acc[1][wi] = b1; }
    }

    const u64* wsm64 = (const u64*)wsm;

    for (int c = 0; c < 64; ++c) {
        __syncthreads();
        // x slab for this channel (zero padding at all borders)
        for (int i = tid; i < 306; i += 256) {
            int kd = i / 102; int r = i - kd * 102;
            int kh = r / 34;  int ii = r - kh * 34;
            int dd = d + kd - 1, hh = h + kh - 1, ww = ii - 1;
            float v = 0.f;
            if ((unsigned)dd < 32u && (unsigned)hh < 32u && (unsigned)ww < 32u)
                v = g_w1[c * N3 + dd * 1024 + hh * 32 + ww];
            xs[i] = v;
        }
        // weight slice for this channel: coalesced float4 copy
        {
            const float4* src = (const float4*)(g_wt + c * 5832);
            float4* dst = (float4*)wsm;
            for (int i = tid; i < 1458; i += 256) dst[i] = src[i];
        }
        __syncthreads();

#pragma unroll
        for (int kk = 0; kk < 9; ++kk) {   // kk = kd*3+kh
            const float* row = &xs[kk * 34 + w0];
            u64 xd[10];
#pragma unroll
            for (int i = 0; i < 10; ++i) { float xv = row[i]; xd[i] = pk2(xv, xv); }
#pragma unroll
            for (int kw = 0; kw < 3; ++kw) {
                int t = kk * 3 + kw;
                u64 wp0 = wsm64[t * 108 + op];
#pragma unroll
                for (int wi = 0; wi < 8; ++wi)
                    acc[0][wi] = ffma2(xd[wi + kw], wp0, acc[0][wi]);
                if (has2) {
                    u64 wp1 = wsm64[t * 108 + 64 + op];
#pragma unroll
                    for (int wi = 0; wi < 8; ++wi)
                        acc[1][wi] = ffma2(xd[wi + kw], wp1, acc[1][wi]);
                }
            }
        }
    }

    int base = d * 1024 + h * 32 + w0;
#pragma unroll
    for (int j = 0; j < 2; ++j) {
        if (j == 1 && !has2) continue;
        int ob = (j == 0) ? (2 * op) : (128 + 2 * op);
        float lo[8], hi[8];
#pragma unroll
        for (int wi = 0; wi < 8; ++wi) upk2(acc[j][wi], lo[wi], hi[wi]);
        float4* pa = (float4*)&g_w2[ob * N3 + base];
        pa[0] = make_float4(lo[0], lo[1], lo[2], lo[3]);
        pa[1] = make_float4(lo[4], lo[5], lo[6], lo[7]);
        float4* pb = (float4*)&g_w2[(ob + 1) * N3 + base];
        pb[0] = make_float4(hi[0], hi[1], hi[2], hi[3]);
        pb[1] = make_float4(hi[4], hi[5], hi[6], hi[7]);
    }
}

// ---------------------------------------------------------------------------
// Kernel 3: fused pixelshuffle + softmax(27) + reassembly + 1x1x1 projection.
// Block = one coarse (d,h) row; 256 threads = 8 fine offsets x 32 w.
// ---------------------------------------------------------------------------
__global__ __launch_bounds__(256) void k_reassemble(const float* __restrict__ x,
                                                    const float* __restrict__ Wp,
                                                    float* __restrict__ out) {
    __shared__ float xs[16 * 306];             // 16 channels, replicate-padded
    __shared__ __align__(16) float ps[2048];   // proj weights [c][oc]
    int tid = threadIdx.x;
    int h = blockIdx.x, d = blockIdx.y;
    int w = tid & 31;
    int off = tid >> 5;                        // = pd*4 + qh*2 + rw
    int pd = off >> 2, qh = (off >> 1) & 1, rw = off & 1;

    for (int i = tid; i < 2048; i += 256) {
        int c = i >> 5, oc = i & 31;
        ps[i] = Wp[oc * 64 + c];
    }

    // softmax over the 27 kernel taps (channel = k*8 + off after pixelshuffle)
    float sw[27];
    int cbase = d * 1024 + h * 32 + w;
    float m = -1e30f;
#pragma unroll
    for (int k = 0; k < 27; ++k) {
        float v = g_w2[(k * 8 + off) * N3 + cbase];
        sw[k] = v;
        m = fmaxf(m, v);
    }
    float s = 0.f;
#pragma unroll
    for (int k = 0; k < 27; ++k) { sw[k] = __expf(sw[k] - m); s += sw[k]; }
    float inv = 1.f / s;
#pragma unroll
    for (int k = 0; k < 27; ++k) sw[k] *= inv;

    const u64* ps64 = (const u64*)ps;
    u64 o2[16];
#pragma unroll
    for (int p = 0; p < 16; ++p) o2[p] = 0ull;

    for (int cb = 0; cb < 4; ++cb) {
        __syncthreads();
        for (int i = tid; i < 16 * 306; i += 256) {
            int c = i / 306;  int r = i - c * 306;
            int kd = r / 102; int r2 = r - kd * 102;
            int kh = r2 / 34; int ii = r2 - kh * 34;
            int dd = min(max(d + kd - 1, 0), 31);
            int hh = min(max(h + kh - 1, 0), 31);
            int ww = min(max(ii - 1, 0), 31);
            xs[i] = x[(cb * 16 + c) * N3 + dd * 1024 + hh * 32 + ww];
        }
        __syncthreads();
#pragma unroll 2
        for (int c = 0; c < 16; ++c) {
            const float* bx = &xs[c * 306 + w];
            float f = 0.f;
#pragma unroll
            for (int kk = 0; kk < 9; ++kk) {
                const float* r = bx + kk * 34;
                f = fmaf(sw[kk * 3 + 0], r[0], f);
                f = fmaf(sw[kk * 3 + 1], r[1], f);
                f = fmaf(sw[kk * 3 + 2], r[2], f);
            }
            u64 fd = pk2(f, f);
            int pc = (cb * 16 + c) * 16;
#pragma unroll
            for (int p = 0; p < 16; ++p) o2[p] = ffma2(fd, ps64[pc + p], o2[p]);
        }
    }

    int d2 = 2 * d + pd, h2 = 2 * h + qh, w2 = 2 * w + rw;
    int fbase = d2 * 4096 + h2 * 64 + w2;
#pragma unroll
    for (int p = 0; p < 16; ++p) {
        float a, b; upk2(o2[p], a, b);
        out[(2 * p) * NF + fbase]     = a;
        out[(2 * p + 1) * NF + fbase] = b;
    }
}

// ---------------------------------------------------------------------------
extern "C" void kernel_launch(void* const* d_in, const int* in_sizes, int n_in,
                              void* d_out, int out_size) {
    const float* x  = (const float*)d_in[0];
    const float* wc = (const float*)d_in[1];
    const float* bc = (const float*)d_in[2];
    const float* we = (const float*)d_in[3];
    const float* be = (const float*)d_in[4];
    const float* wp = (const float*)d_in[5];
    float* out = (float*)d_out;

    k_compress<<<128, 256>>>(x, wc, bc);
    k_wtrans<<<1458, 256>>>(we);              // 1458*256 == 216*64*27 exactly
    k_encode<<<dim3(32, 32), 256>>>(be);
    k_reassemble<<<dim3(32, 32), 256>>>(x, wp, out);
}

// round 2
// speedup vs baseline: 1.0065x; 1.0065x over previous
#include <cuda_runtime.h>

// CARAFE3d: B=1, C=64, D=H=W=32, c_mid=64, s=2, k=3, out_ch=32
// fine grid 64^3, encode channels 216 = 8*27.

#define N3 32768      // 32^3 coarse voxels
#define NF 262144     // 64^3 fine voxels

__device__ float g_w1[64 * N3];          // compressed features [c_mid][32^3]
__device__ float g_w2[216 * N3];         // encode output       [216][32^3]
__device__ float g_wt[64 * 27 * 216];    // transposed encode weights [c][t][o]

typedef unsigned long long u64;
__device__ u64 g_p2[16 * N3];            // projected x, oc-pairs packed: (2p,2p+1)

__device__ __forceinline__ u64 pk2(float lo, float hi) {
    u64 r; asm("mov.b64 %0, {%1, %2};" : "=l"(r) : "f"(lo), "f"(hi)); return r;
}
__device__ __forceinline__ void upk2(u64 v, float& lo, float& hi) {
    asm("mov.b64 {%0, %1}, %2;" : "=f"(lo), "=f"(hi) : "l"(v));
}
__device__ __forceinline__ u64 ffma2(u64 a, u64 b, u64 c) {
    u64 d; asm("fma.rn.f32x2 %0, %1, %2, %3;" : "=l"(d) : "l"(a), "l"(b), "l"(c));
    return d;
}
__device__ __forceinline__ void cp_async16(void* smem_dst, const void* gsrc) {
    unsigned dst = (unsigned)__cvta_generic_to_shared(smem_dst);
    asm volatile("cp.async.ca.shared.global [%0], [%1], 16;\n" :: "r"(dst), "l"(gsrc));
}

// ---------------------------------------------------------------------------
// Kernel 1: 1x1x1 compress conv.  g_w1[cm][v] = sum_c Wc[cm][c]*x[c][v] + b[cm]
// ---------------------------------------------------------------------------
__global__ __launch_bounds__(256) void k_compress(const float* __restrict__ x,
                                                  const float* __restrict__ Wc,
                                                  const float* __restrict__ bc) {
    __shared__ __align__(16) float Ws[64 * 64];   // [c][cm]
    __shared__ float bs[64];
    int tid = threadIdx.x;
    for (int i = tid; i < 4096; i += 256) {
        int c = i >> 6, cm = i & 63;
        Ws[i] = Wc[cm * 64 + c];
    }
    if (tid < 64) bs[tid] = bc[tid];
    __syncthreads();

    int v = blockIdx.x * 256 + tid;
    const u64* ws64 = (const u64*)Ws;
    u64 acc[32];
#pragma unroll
    for (int p = 0; p < 32; ++p) acc[p] = pk2(bs[2 * p], bs[2 * p + 1]);

#pragma unroll 2
    for (int c = 0; c < 64; ++c) {
        float xv = x[c * N3 + v];
        u64 xd = pk2(xv, xv);
#pragma unroll
        for (int p = 0; p < 32; ++p) acc[p] = ffma2(xd, ws64[c * 32 + p], acc[p]);
    }
#pragma unroll
    for (int p = 0; p < 32; ++p) {
        float a, b; upk2(acc[p], a, b);
        g_w1[(2 * p) * N3 + v]     = a;
        g_w1[(2 * p + 1) * N3 + v] = b;
    }
}

// ---------------------------------------------------------------------------
// Kernel 1p: 1x1x1 projection applied to x DIRECTLY (commutes with the patch
// gather since projection is channel-only).  g_p2[p][v] = (proj[2p], proj[2p+1])
// ---------------------------------------------------------------------------
__global__ __launch_bounds__(256) void k_proj(const float* __restrict__ x,
                                              const float* __restrict__ Wp) {
    __shared__ __align__(16) float Ws[64 * 32];   // [c][oc]
    int tid = threadIdx.x;
    for (int i = tid; i < 2048; i += 256) {
        int c = i >> 5, oc = i & 31;
        Ws[i] = Wp[oc * 64 + c];
    }
    __syncthreads();

    int v = blockIdx.x * 256 + tid;
    const u64* ws64 = (const u64*)Ws;
    u64 acc[16];
#pragma unroll
    for (int p = 0; p < 16; ++p) acc[p] = 0ull;
#pragma unroll 2
    for (int c = 0; c < 64; ++c) {
        float xv = x[c * N3 + v];
        u64 xd = pk2(xv, xv);
#pragma unroll
        for (int p = 0; p < 16; ++p) acc[p] = ffma2(xd, ws64[c * 16 + p], acc[p]);
    }
#pragma unroll
    for (int p = 0; p < 16; ++p) g_p2[p * N3 + v] = acc[p];
}

// ---------------------------------------------------------------------------
// Kernel 1b: transpose encode weights [o][c][t] -> [c][t][o]
// ---------------------------------------------------------------------------
__global__ __launch_bounds__(256) void k_wtrans(const float* __restrict__ We) {
    int id = blockIdx.x * 256 + threadIdx.x;   // id = c*5832 + t*216 + o
    int c = id / 5832;
    int r = id - c * 5832;
    int t = r / 216;
    int o = r - t * 216;
    g_wt[id] = We[o * 1728 + c * 27 + t];
}

// ---------------------------------------------------------------------------
// Kernel 2: 3x3x3 encode conv (zero pad).  THE hot kernel (12.2 GMAC).
// Block = (d, 2 h-rows, all 32 w), all 216 outputs.  224 threads:
//   wq = tid&7 -> 4 consecutive w;  pg = tid>>3 (0..26 active) -> 4 oc-pairs
//   (channels 8pg..8pg+7).  Weights double-buffered via cp.async; x slab
//   stored pre-duplicated as (x,x) u64 so FFMA2 needs no packing movs.
// ---------------------------------------------------------------------------
__global__ __launch_bounds__(224, 2) void k_encode(const float* __restrict__ be) {
    extern __shared__ __align__(16) char dsm[];
    u64*   xsd = (u64*)dsm;                 // 2 x 408  ([kd][kh4][34], dup'd)
    float* wsm = (float*)(dsm + 2 * 408 * 8);  // 2 x 5832 ([t][216])

    int tid = threadIdx.x;
    int h0 = blockIdx.x * 2, d = blockIdx.y;
    int wq = tid & 7, pg = tid >> 3;        // pg 0..27 (27 inactive)
    int w0 = wq * 4;
    bool act = (pg < 27);

    u64 acc[2][4][4];                       // [row][pair j][wi]
    if (act) {
#pragma unroll
        for (int j = 0; j < 4; ++j) {
            u64 b = pk2(be[8 * pg + 2 * j], be[8 * pg + 2 * j + 1]);
#pragma unroll
            for (int wi = 0; wi < 4; ++wi) { acc[0][j][wi] = b; acc[1][j][wi] = b; }
        }
    }

    // prologue: prefetch c=0
    {
        const float4* src = (const float4*)g_wt;
        for (int i = tid; i < 1458; i += 224) cp_async16(&wsm[i * 4], src + i);
        asm volatile("cp.async.commit_group;\n");
        for (int i = tid; i < 408; i += 224) {
            int kd = i / 136; int r = i - kd * 136;
            int kh = r / 34;  int ii = r - kh * 34;
            int dd = d + kd - 1, hh = h0 + kh - 1, ww = ii - 1;
            float v = 0.f;
            if ((unsigned)dd < 32u && (unsigned)hh < 32u && (unsigned)ww < 32u)
                v = g_w1[dd * 1024 + hh * 32 + ww];
            xsd[i] = pk2(v, v);
        }
        asm volatile("cp.async.wait_group 0;\n");
        __syncthreads();
    }

    for (int c = 0; c < 64; ++c) {
        int cur = c & 1, nxt = cur ^ 1;
        if (c < 63) {
            const float4* src = (const float4*)(g_wt + (c + 1) * 5832);
            float* wdst = wsm + nxt * 5832;
            for (int i = tid; i < 1458; i += 224) cp_async16(&wdst[i * 4], src + i);
            asm volatile("cp.async.commit_group;\n");
            u64* sdst = xsd + nxt * 408;
            const float* xsrc = g_w1 + (c + 1) * N3;
            for (int i = tid; i < 408; i += 224) {
                int kd = i / 136; int r = i - kd * 136;
                int kh = r / 34;  int ii = r - kh * 34;
                int dd = d + kd - 1, hh = h0 + kh - 1, ww = ii - 1;
                float v = 0.f;
                if ((unsigned)dd < 32u && (unsigned)hh < 32u && (unsigned)ww < 32u)
                    v = xsrc[dd * 1024 + hh * 32 + ww];
                sdst[i] = pk2(v, v);
            }
        }
        if (act) {
            const u64* wb = (const u64*)(wsm + cur * 5832);
            const u64* xb = xsd + cur * 408;
#pragma unroll
            for (int kd = 0; kd < 3; ++kd) {
#pragma unroll
                for (int kh = 0; kh < 3; ++kh) {
                    const u64* r0 = &xb[kd * 136 + kh * 34 + w0];
                    u64 x0[6], x1[6];
#pragma unroll
                    for (int i = 0; i < 6; ++i) { x0[i] = r0[i]; x1[i] = r0[i + 34]; }
#pragma unroll
                    for (int kw = 0; kw < 3; ++kw) {
                        int t = (kd * 3 + kh) * 3 + kw;
                        const u64* wp = &wb[t * 108 + 4 * pg];
                        u64 wv0 = wp[0], wv1 = wp[1], wv2 = wp[2], wv3 = wp[3];
#pragma unroll
                        for (int wi = 0; wi < 4; ++wi) {
                            acc[0][0][wi] = ffma2(x0[wi + kw], wv0, acc[0][0][wi]);
                            acc[0][1][wi] = ffma2(x0[wi + kw], wv1, acc[0][1][wi]);
                            acc[0][2][wi] = ffma2(x0[wi + kw], wv2, acc[0][2][wi]);
                            acc[0][3][wi] = ffma2(x0[wi + kw], wv3, acc[0][3][wi]);
                            acc[1][0][wi] = ffma2(x1[wi + kw], wv0, acc[1][0][wi]);
                            acc[1][1][wi] = ffma2(x1[wi + kw], wv1, acc[1][1][wi]);
                            acc[1][2][wi] = ffma2(x1[wi + kw], wv2, acc[1][2][wi]);
                            acc[1][3][wi] = ffma2(x1[wi + kw], wv3, acc[1][3][wi]);
                        }
                    }
                }
            }
        }
        if (c < 63) asm volatile("cp.async.wait_group 0;\n");
        __syncthreads();
    }

    if (act) {
#pragma unroll
        for (int r = 0; r < 2; ++r) {
            int base = d * 1024 + (h0 + r) * 32 + w0;
#pragma unroll
            for (int j = 0; j < 4; ++j) {
                float lo[4], hi[4];
#pragma unroll
                for (int wi = 0; wi < 4; ++wi) upk2(acc[r][j][wi], lo[wi], hi[wi]);
                int ch = 8 * pg + 2 * j;
                *(float4*)&g_w2[ch * N3 + base]       = make_float4(lo[0], lo[1], lo[2], lo[3]);
                *(float4*)&g_w2[(ch + 1) * N3 + base] = make_float4(hi[0], hi[1], hi[2], hi[3]);
            }
        }
    }
}

// ---------------------------------------------------------------------------
// Kernel 3: fused pixelshuffle + softmax(27) + FACTORED reassembly.
// out(oc,fine) = sum_t softmax_t(fine) * p(oc, shift_t(coarse)), p = Wp*x.
// Block = one coarse (d,h) row; 256 threads = 8 fine offsets x 32 w.
// ---------------------------------------------------------------------------
__global__ __launch_bounds__(256) void k_reassemble(float* __restrict__ out) {
    __shared__ __align__(16) u64 ps[16 * 306];  // p-pairs slab [pp][kd][kh][34]
    int tid = threadIdx.x;
    int h = blockIdx.x, d = blockIdx.y;
    int w = tid & 31;
    int off = tid >> 5;                        // = pd*4 + qh*2 + rw
    int pd = off >> 2, qh = (off >> 1) & 1, rw = off & 1;

    // fill projected-patch slab (replicate padding)
    for (int i = tid; i < 16 * 306; i += 256) {
        int pp = i / 306; int r = i - pp * 306;
        int kd = r / 102; int r2 = r - kd * 102;
        int kh = r2 / 34; int ii = r2 - kh * 34;
        int dd = min(max(d + kd - 1, 0), 31);
        int hh = min(max(h + kh - 1, 0), 31);
        int ww = min(max(ii - 1, 0), 31);
        ps[i] = g_p2[pp * N3 + dd * 1024 + hh * 32 + ww];
    }

    // softmax over the 27 kernel taps (channel = k*8 + off after pixelshuffle)
    float sw[27];
    int cbase = d * 1024 + h * 32 + w;
    float m = -1e30f;
#pragma unroll
    for (int k = 0; k < 27; ++k) {
        float v = g_w2[(k * 8 + off) * N3 + cbase];
        sw[k] = v;
        m = fmaxf(m, v);
    }
    float s = 0.f;
#pragma unroll
    for (int k = 0; k < 27; ++k) { sw[k] = __expf(sw[k] - m); s += sw[k]; }
    float inv = 1.f / s;
#pragma unroll
    for (int k = 0; k < 27; ++k) sw[k] *= inv;

    __syncthreads();

    u64 acc[16];
#pragma unroll
    for (int p = 0; p < 16; ++p) acc[p] = 0ull;

#pragma unroll
    for (int kd = 0; kd < 3; ++kd) {
#pragma unroll
        for (int kh = 0; kh < 3; ++kh) {
#pragma unroll
            for (int kw = 0; kw < 3; ++kw) {
                float sv = sw[(kd * 3 + kh) * 3 + kw];
                u64 sd = pk2(sv, sv);
                int base = kd * 102 + kh * 34 + w + kw;
#pragma unroll
                for (int p = 0; p < 16; ++p)
                    acc[p] = ffma2(sd, ps[p * 306 + base], acc[p]);
            }
        }
    }

    int d2 = 2 * d + pd, h2 = 2 * h + qh, w2 = 2 * w + rw;
    int fbase = d2 * 4096 + h2 * 64 + w2;
#pragma unroll
    for (int p = 0; p < 16; ++p) {
        float a, b; upk2(acc[p], a, b);
        out[(2 * p) * NF + fbase]     = a;
        out[(2 * p + 1) * NF + fbase] = b;
    }
}

// ---------------------------------------------------------------------------
extern "C" void kernel_launch(void* const* d_in, const int* in_sizes, int n_in,
                              void* d_out, int out_size) {
    const float* x  = (const float*)d_in[0];
    const float* wc = (const float*)d_in[1];
    const float* bc = (const float*)d_in[2];
    const float* we = (const float*)d_in[3];
    const float* be = (const float*)d_in[4];
    const float* wp = (const float*)d_in[5];
    float* out = (float*)d_out;

    static int smem_set = 0;
    const int enc_smem = 2 * 5832 * 4 + 2 * 408 * 8;   // 53184 B
    if (!smem_set) {
        cudaFuncSetAttribute(k_encode, cudaFuncAttributeMaxDynamicSharedMemorySize,
                             enc_smem);
        smem_set = 1;
    }

    k_compress<<<128, 256>>>(x, wc, bc);
    k_proj<<<128, 256>>>(x, wp);
    k_wtrans<<<1458, 256>>>(we);              // 1458*256 == 216*64*27 exactly
    k_encode<<<dim3(16, 32), 224, enc_smem>>>(be);
    k_reassemble<<<dim3(32, 32), 256>>>(out);
}

// round 4
// speedup vs baseline: 2.3295x; 2.3145x over previous
#include <cuda_runtime.h>
#include <cuda_bf16.h>
#include <stdint.h>

// CARAFE3d: B=1, C=64, D=H=W=32, c_mid=64, s=2, k=3, out_ch=32
#define N3 32768      // 32^3 coarse voxels
#define NF 262144     // 64^3 fine voxels

typedef unsigned long long u64;

// ---------------- global scratch ----------------
__device__ __align__(16) __nv_bfloat16 g_xh[N3 * 64];        // compressed feats hi, [v][c]
__device__ __align__(16) __nv_bfloat16 g_xl[N3 * 64];        // residual lo,        [v][c]
__device__ __align__(16) __nv_bfloat16 g_wbh[27 * 216 * 64]; // weights hi [t][o][c], pre-swizzled
__device__ __align__(16) __nv_bfloat16 g_wbl[27 * 216 * 64]; // weights lo
__device__ float g_w2[N3 * 216];                             // encode output, VOXEL-major [v][ch]
__device__ u64   g_p2[16 * N3];                              // projected x, oc-pairs

// ---------------- helpers ----------------
__device__ __forceinline__ u64 pk2(float lo, float hi) {
    u64 r; asm("mov.b64 %0, {%1, %2};" : "=l"(r) : "f"(lo), "f"(hi)); return r;
}
__device__ __forceinline__ void upk2(u64 v, float& lo, float& hi) {
    asm("mov.b64 {%0, %1}, %2;" : "=f"(lo), "=f"(hi) : "l"(v));
}
__device__ __forceinline__ u64 ffma2(u64 a, u64 b, u64 c) {
    u64 d; asm("fma.rn.f32x2 %0, %1, %2, %3;" : "=l"(d) : "l"(a), "l"(b), "l"(c));
    return d;
}
__device__ __forceinline__ unsigned bfpk(float lo, float hi) {  // mem order: lo first
    unsigned r; asm("cvt.rn.bf16x2.f32 %0, %1, %2;" : "=r"(r) : "f"(hi), "f"(lo));
    return r;
}
__device__ __forceinline__ void cp16(uint32_t dst, const void* src) {
    asm volatile("cp.async.ca.shared.global [%0], [%1], 16;" :: "r"(dst), "l"(src));
}
__device__ __forceinline__ void ldsm4(uint32_t* r, uint32_t addr) {
    asm volatile("ldmatrix.sync.aligned.m8n8.x4.shared.b16 {%0,%1,%2,%3}, [%4];"
                 : "=r"(r[0]), "=r"(r[1]), "=r"(r[2]), "=r"(r[3]) : "r"(addr));
}
__device__ __forceinline__ void ldsm2(uint32_t* r, uint32_t addr) {
    asm volatile("ldmatrix.sync.aligned.m8n8.x2.shared.b16 {%0,%1}, [%2];"
                 : "=r"(r[0]), "=r"(r[1]) : "r"(addr));
}
__device__ __forceinline__ void mma16816(float* c, const uint32_t* a, const uint32_t* b) {
    asm volatile("mma.sync.aligned.m16n8k16.row.col.f32.bf16.bf16.f32 "
                 "{%0,%1,%2,%3}, {%4,%5,%6,%7}, {%8,%9}, {%0,%1,%2,%3};"
                 : "+f"(c[0]), "+f"(c[1]), "+f"(c[2]), "+f"(c[3])
                 : "r"(a[0]), "r"(a[1]), "r"(a[2]), "r"(a[3]), "r"(b[0]), "r"(b[1]));
}

// ---------------------------------------------------------------------------
// Kernel 1: 1x1x1 compress conv -> bf16 hi/lo split, voxel-major [v][64c]
// ---------------------------------------------------------------------------
__global__ __launch_bounds__(256) void k_compress(const float* __restrict__ x,
                                                  const float* __restrict__ Wc,
                                                  const float* __restrict__ bc) {
    __shared__ __align__(16) float Ws[64 * 64];   // [c][cm]
    __shared__ float bs[64];
    int tid = threadIdx.x;
    for (int i = tid; i < 4096; i += 256) {
        int c = i >> 6, cm = i & 63;
        Ws[i] = Wc[cm * 64 + c];
    }
    if (tid < 64) bs[tid] = bc[tid];
    __syncthreads();

    int v = blockIdx.x * 256 + tid;
    const u64* ws64 = (const u64*)Ws;
    u64 acc[32];
#pragma unroll
    for (int p = 0; p < 32; ++p) acc[p] = pk2(bs[2 * p], bs[2 * p + 1]);
#pragma unroll 2
    for (int c = 0; c < 64; ++c) {
        float xv = x[c * N3 + v];
        u64 xd = pk2(xv, xv);
#pragma unroll
        for (int p = 0; p < 32; ++p) acc[p] = ffma2(xd, ws64[c * 32 + p], acc[p]);
    }
    float vals[64];
#pragma unroll
    for (int p = 0; p < 32; ++p) upk2(acc[p], vals[2 * p], vals[2 * p + 1]);

    uint4* xh4 = (uint4*)g_xh;
    uint4* xl4 = (uint4*)g_xl;
#pragma unroll
    for (int i = 0; i < 8; ++i) {
        unsigned hw[4], lw[4];
#pragma unroll
        for (int j = 0; j < 4; ++j) {
            float a = vals[i * 8 + 2 * j], b = vals[i * 8 + 2 * j + 1];
            float ah = __bfloat162float(__float2bfloat16(a));
            float bh = __bfloat162float(__float2bfloat16(b));
            hw[j] = bfpk(a, b);
            lw[j] = bfpk(a - ah, b - bh);
        }
        xh4[v * 8 + i] = make_uint4(hw[0], hw[1], hw[2], hw[3]);
        xl4[v * 8 + i] = make_uint4(lw[0], lw[1], lw[2], lw[3]);
    }
}

// ---------------------------------------------------------------------------
// Kernel 1p: 1x1x1 projection of x (commutes with patch gather)
// ---------------------------------------------------------------------------
__global__ __launch_bounds__(256) void k_proj(const float* __restrict__ x,
                                              const float* __restrict__ Wp) {
    __shared__ __align__(16) float Ws[64 * 32];   // [c][oc]
    int tid = threadIdx.x;
    for (int i = tid; i < 2048; i += 256) {
        int c = i >> 5, oc = i & 31;
        Ws[i] = Wp[oc * 64 + c];
    }
    __syncthreads();
    int v = blockIdx.x * 256 + tid;
    const u64* ws64 = (const u64*)Ws;
    u64 acc[16];
#pragma unroll
    for (int p = 0; p < 16; ++p) acc[p] = 0ull;
#pragma unroll 2
    for (int c = 0; c < 64; ++c) {
        float xv = x[c * N3 + v];
        u64 xd = pk2(xv, xv);
#pragma unroll
        for (int p = 0; p < 16; ++p) acc[p] = ffma2(xd, ws64[c * 16 + p], acc[p]);
    }
#pragma unroll
    for (int p = 0; p < 16; ++p) g_p2[p * N3 + v] = acc[p];
}

// ---------------------------------------------------------------------------
// Kernel 1w: encode weights -> [t][o][c] bf16 hi/lo, PRE-SWIZZLED (SW128) so
// a linear copy into smem lands in ldmatrix layout.  chunk ci -> ci^(o&7).
// ---------------------------------------------------------------------------
__global__ __launch_bounds__(256) void k_wprep(const float* __restrict__ We) {
    int id = blockIdx.x * 256 + threadIdx.x;   // 27*216*64 = 373248
    int t = id / 13824;
    int r = id - t * 13824;
    int o = r >> 6, c = r & 63;
    float v = We[o * 1728 + c * 27 + t];
    __nv_bfloat16 h = __float2bfloat16(v);
    float rf = v - __bfloat162float(h);
    int ci = c >> 3, j = c & 7;
    int dst = t * 13824 + o * 64 + ((ci ^ (o & 7)) << 3) + j;
    g_wbh[dst] = h;
    g_wbl[dst] = __float2bfloat16(rf);
}

// ---------------------------------------------------------------------------
// Kernel 2: encode conv as mma.sync bf16x3 GEMM (legacy HMMA path — no
// tcgen05 available under the harness's compute_100 virtual arch).
// Per CTA: M=128 voxels (d fixed, 4 h-rows x 32 w), N=216, K = 27 taps x 64c.
// 8 warps: warp w -> m-rows 16w..16w+15, full N.  Accumulators: 108 f32/thr.
// Double-buffered stages (cp.async + syncthreads, proven pattern).
// ---------------------------------------------------------------------------
#define A_TILE 16384                 // 128 rows x 128 B (one of hi/lo)
#define B_OFF  32768
#define B_TILE 27648                 // 216 rows x 128 B
#define STG_SZ 88064                 // Ah Al Bh Bl

__device__ __forceinline__ void build_stage(uint32_t stage, int t, int tid,
                                            int d, int h0) {
    const char* srcH = (const char*)g_wbh + t * B_TILE;
    const char* srcL = (const char*)g_wbl + t * B_TILE;
    for (int i = tid; i < 1728; i += 256) {
        cp16(stage + B_OFF + i * 16, srcH + i * 16);
        cp16(stage + B_OFF + B_TILE + i * 16, srcL + i * 16);
    }
    int kd = t / 9; int rr = t - kd * 9; int kh = rr / 3; int kw = rr - kh * 3;
    const uint4* xh4 = (const uint4*)g_xh;
    const uint4* xl4 = (const uint4*)g_xl;
#pragma unroll
    for (int it = 0; it < 4; ++it) {
        int idx = tid + it * 256;            // 0..1023: row m (7b) x chunk ci (3b)
        int m = idx >> 3, ci = idx & 7;
        int hr = m >> 5, w = m & 31;
        int dd = d + kd - 1, hh = h0 + hr + kh - 1, ww = w + kw - 1;
        uint4 vh = make_uint4(0, 0, 0, 0), vl = vh;
        if ((unsigned)dd < 32u && (unsigned)hh < 32u && (unsigned)ww < 32u) {
            int v = dd * 1024 + hh * 32 + ww;
            vh = xh4[v * 8 + ci];
            vl = xl4[v * 8 + ci];
        }
        uint32_t dst = stage + m * 128 + ((ci ^ (m & 7)) << 4);
        asm volatile("st.shared.v4.b32 [%0], {%1,%2,%3,%4};" :: "r"(dst),
                     "r"(vh.x), "r"(vh.y), "r"(vh.z), "r"(vh.w) : "memory");
        asm volatile("st.shared.v4.b32 [%0], {%1,%2,%3,%4};" :: "r"(dst + A_TILE),
                     "r"(vl.x), "r"(vl.y), "r"(vl.z), "r"(vl.w) : "memory");
    }
    asm volatile("cp.async.commit_group;" ::: "memory");
}

__global__ __launch_bounds__(256, 1) void k_encode_mma(const float* __restrict__ be) {
    extern __shared__ char dsraw[];
    char* dsm = (char*)(((uintptr_t)dsraw + 1023) & ~(uintptr_t)1023);
    uint32_t s_base = (uint32_t)__cvta_generic_to_shared(dsm);
    __shared__ float bias[216];

    int tid = threadIdx.x;
    int wid = tid >> 5, lane = tid & 31;
    int b = blockIdx.x;
    int d = b >> 3, h0 = (b & 7) << 2;

    for (int i = tid; i < 216; i += 256) bias[i] = be[i];

    // ldmatrix per-lane address components
    int ar   = wid * 16 + (lane & 15);   // A tile row (m)
    int akh  = lane >> 4;                // A k-half
    int axor = ar & 7;
    int brn  = lane & 7;                 // B row within ntile
    int bkh  = (lane >> 3) & 1;

    float acc[108];
#pragma unroll
    for (int i = 0; i < 108; ++i) acc[i] = 0.f;

    build_stage(s_base, 0, tid, d, h0);
    asm volatile("cp.async.wait_group 0;" ::: "memory");
    __syncthreads();

    for (int t = 0; t < 27; ++t) {
        int s = t & 1;
        if (t + 1 < 27) build_stage(s_base + (s ^ 1) * STG_SZ, t + 1, tid, d, h0);

        uint32_t stage = s_base + s * STG_SZ;
        uint32_t abase = stage + ar * 128;
#pragma unroll 1
        for (int ks = 0; ks < 4; ++ks) {
            uint32_t ah[4], al[4];
            uint32_t aaddr = abase + (((((ks << 1) | akh)) ^ axor) << 4);
            ldsm4(ah, aaddr);
            ldsm4(al, aaddr + A_TILE);
            uint32_t bbase = stage + B_OFF + brn * 128 +
                             (((((ks << 1) | bkh)) ^ brn) << 4);
#pragma unroll
            for (int n = 0; n < 27; ++n) {
                uint32_t bh[2], bl[2];
                ldsm2(bh, bbase + n * 1024);
                ldsm2(bl, bbase + n * 1024 + B_TILE);
                mma16816(&acc[4 * n], ah, bh);
                mma16816(&acc[4 * n], ah, bl);
                mma16816(&acc[4 * n], al, bh);
            }
        }
        if (t + 1 < 27) asm volatile("cp.async.wait_group 0;" ::: "memory");
        __syncthreads();
    }

    // epilogue: c-frag -> g_w2 voxel-major [v][216] with bias, 8B v2 stores
    int g = lane >> 2, tq = lane & 3;
    int vbase = d * 1024 + h0 * 32;      // + m (m = row within CTA, contiguous v)
    int r0 = wid * 16 + g;
#pragma unroll
    for (int n = 0; n < 27; ++n) {
        int c0 = n * 8 + 2 * tq;
        float b0v = bias[c0], b1v = bias[c0 + 1];
        *(float2*)&g_w2[(u64)(vbase + r0) * 216 + c0] =
            make_float2(acc[4 * n] + b0v, acc[4 * n + 1] + b1v);
        *(float2*)&g_w2[(u64)(vbase + r0 + 8) * 216 + c0] =
            make_float2(acc[4 * n + 2] + b0v, acc[4 * n + 3] + b1v);
    }
}

// ---------------------------------------------------------------------------
// Kernel 3: fused pixelshuffle + softmax(27) + factored reassembly.
// w2 is voxel-major now: stage the block's 32x216 slab in smem (217-padded,
// conflict-free softmax reads).
// ---------------------------------------------------------------------------
__global__ __launch_bounds__(256) void k_reassemble(float* __restrict__ out) {
    extern __shared__ char rsm[];
    u64*   ps  = (u64*)rsm;                       // 16*306 u64
    float* w2s = (float*)(rsm + 16 * 306 * 8);    // 32*217 floats

    int tid = threadIdx.x;
    int h = blockIdx.x, d = blockIdx.y;
    int w = tid & 31;
    int off = tid >> 5;
    int pd = off >> 2, qh = (off >> 1) & 1, rw = off & 1;
    int vbase = d * 1024 + h * 32;

    // stage encode-output slab: fully contiguous gmem read
    for (int i = tid; i < 6912; i += 256) {
        int vr = i / 216, ch = i - vr * 216;
        w2s[vr * 217 + ch] = g_w2[(u64)vbase * 216 + i];
    }
    // projected-patch slab (replicate padding)
    for (int i = tid; i < 16 * 306; i += 256) {
        int pp = i / 306; int r = i - pp * 306;
        int kd = r / 102; int r2 = r - kd * 102;
        int kh = r2 / 34; int ii = r2 - kh * 34;
        int dd = min(max(d + kd - 1, 0), 31);
        int hh = min(max(h + kh - 1, 0), 31);
        int ww = min(max(ii - 1, 0), 31);
        ps[i] = g_p2[pp * N3 + dd * 1024 + hh * 32 + ww];
    }
    __syncthreads();

    float sw[27];
    float m = -1e30f;
#pragma unroll
    for (int k = 0; k < 27; ++k) {
        float v = w2s[w * 217 + k * 8 + off];
        sw[k] = v;
        m = fmaxf(m, v);
    }
    float s = 0.f;
#pragma unroll
    for (int k = 0; k < 27; ++k) { sw[k] = __expf(sw[k] - m); s += sw[k]; }
    float inv = 1.f / s;
#pragma unroll
    for (int k = 0; k < 27; ++k) sw[k] *= inv;

    u64 acc[16];
#pragma unroll
    for (int p = 0; p < 16; ++p) acc[p] = 0ull;
#pragma unroll
    for (int kd = 0; kd < 3; ++kd)
#pragma unroll
        for (int kh = 0; kh < 3; ++kh)
#pragma unroll
            for (int kw = 0; kw < 3; ++kw) {
                float sv = sw[(kd * 3 + kh) * 3 + kw];
                u64 sd = pk2(sv, sv);
                int base = kd * 102 + kh * 34 + w + kw;
#pragma unroll
                for (int p = 0; p < 16; ++p)
                    acc[p] = ffma2(sd, ps[p * 306 + base], acc[p]);
            }

    int d2 = 2 * d + pd, h2 = 2 * h + qh, w2 = 2 * w + rw;
    int fbase = d2 * 4096 + h2 * 64 + w2;
#pragma unroll
    for (int p = 0; p < 16; ++p) {
        float a, bb; upk2(acc[p], a, bb);
        out[(2 * p) * NF + fbase]     = a;
        out[(2 * p + 1) * NF + fbase] = bb;
    }
}

// ---------------------------------------------------------------------------
extern "C" void kernel_launch(void* const* d_in, const int* in_sizes, int n_in,
                              void* d_out, int out_size) {
    const float* x  = (const float*)d_in[0];
    const float* wc = (const float*)d_in[1];
    const float* bc = (const float*)d_in[2];
    const float* we = (const float*)d_in[3];
    const float* be = (const float*)d_in[4];
    const float* wp = (const float*)d_in[5];
    float* out = (float*)d_out;

    const int enc_smem = 2 * STG_SZ + 1024;             // 177152
    const int rea_smem = 16 * 306 * 8 + 32 * 217 * 4;   // 66944
    static int smem_set = 0;
    if (!smem_set) {
        cudaFuncSetAttribute(k_encode_mma, cudaFuncAttributeMaxDynamicSharedMemorySize,
                             enc_smem);
        cudaFuncSetAttribute(k_reassemble, cudaFuncAttributeMaxDynamicSharedMemorySize,
                             rea_smem);
        smem_set = 1;
    }

    k_compress<<<128, 256>>>(x, wc, bc);
    k_proj<<<128, 256>>>(x, wp);
    k_wprep<<<1458, 256>>>(we);
    k_encode_mma<<<256, 256, enc_smem>>>(be);
    k_reassemble<<<dim3(32, 32), 256, rea_smem>>>(out);
}

// round 5
// speedup vs baseline: 2.3424x; 1.0056x over previous
#include <cuda_runtime.h>
#include <cuda_bf16.h>
#include <stdint.h>

// CARAFE3d: B=1, C=64, D=H=W=32, c_mid=64, s=2, k=3, out_ch=32
#define N3 32768      // 32^3 coarse voxels
#define NF 262144     // 64^3 fine voxels

typedef unsigned long long u64;

// ---------------- global scratch ----------------
__device__ __align__(16) __nv_bfloat16 g_xh[N3 * 64];        // compressed feats hi, [v][c]
__device__ __align__(16) __nv_bfloat16 g_xl[N3 * 64];        // residual lo,        [v][c]
__device__ __align__(16) __nv_bfloat16 g_wbh[27 * 224 * 64]; // weights hi [t][o(pad224)][c], pre-swizzled
__device__ __align__(16) __nv_bfloat16 g_wbl[27 * 224 * 64]; // weights lo (pad rows stay zero)
__device__ float g_w2[N3 * 216];                             // encode output, voxel-major [v][ch]
__device__ u64   g_p2[16 * N3];                              // projected x, oc-pairs

// ---------------- helpers ----------------
__device__ __forceinline__ u64 pk2(float lo, float hi) {
    u64 r; asm("mov.b64 %0, {%1, %2};" : "=l"(r) : "f"(lo), "f"(hi)); return r;
}
__device__ __forceinline__ void upk2(u64 v, float& lo, float& hi) {
    asm("mov.b64 {%0, %1}, %2;" : "=f"(lo), "=f"(hi) : "l"(v));
}
__device__ __forceinline__ u64 ffma2(u64 a, u64 b, u64 c) {
    u64 d; asm("fma.rn.f32x2 %0, %1, %2, %3;" : "=l"(d) : "l"(a), "l"(b), "l"(c));
    return d;
}
__device__ __forceinline__ unsigned bfpk(float lo, float hi) {  // mem order: lo first
    unsigned r; asm("cvt.rn.bf16x2.f32 %0, %1, %2;" : "=r"(r) : "f"(hi), "f"(lo));
    return r;
}
__device__ __forceinline__ void cp16(uint32_t dst, const void* src) {
    asm volatile("cp.async.ca.shared.global [%0], [%1], 16;" :: "r"(dst), "l"(src));
}
__device__ __forceinline__ void ldsm4(uint32_t* r, uint32_t addr) {
    asm volatile("ldmatrix.sync.aligned.m8n8.x4.shared.b16 {%0,%1,%2,%3}, [%4];"
                 : "=r"(r[0]), "=r"(r[1]), "=r"(r[2]), "=r"(r[3]) : "r"(addr));
}
__device__ __forceinline__ void mma16816(float* c, const uint32_t* a, const uint32_t* b) {
    asm volatile("mma.sync.aligned.m16n8k16.row.col.f32.bf16.bf16.f32 "
                 "{%0,%1,%2,%3}, {%4,%5,%6,%7}, {%8,%9}, {%0,%1,%2,%3};"
                 : "+f"(c[0]), "+f"(c[1]), "+f"(c[2]), "+f"(c[3])
                 : "r"(a[0]), "r"(a[1]), "r"(a[2]), "r"(a[3]), "r"(b[0]), "r"(b[1]));
}

// ---------------------------------------------------------------------------
// Kernel 1: fused 1x1x1 compress (-> bf16 hi/lo, voxel-major) + 1x1x1 proj
// ---------------------------------------------------------------------------
__global__ __launch_bounds__(256) void k_front(const float* __restrict__ x,
                                               const float* __restrict__ Wc,
                                               const float* __restrict__ bc,
                                               const float* __restrict__ Wp) {
    __shared__ __align__(16) float Ws[64 * 64];   // compress [c][cm]
    __shared__ __align__(16) float Ps[64 * 32];   // proj     [c][oc]
    __shared__ float bs[64];
    int tid = threadIdx.x;
    for (int i = tid; i < 4096; i += 256) {
        int c = i >> 6, cm = i & 63;
        Ws[i] = Wc[cm * 64 + c];
    }
    for (int i = tid; i < 2048; i += 256) {
        int c = i >> 5, oc = i & 31;
        Ps[i] = Wp[oc * 64 + c];
    }
    if (tid < 64) bs[tid] = bc[tid];
    __syncthreads();

    int v = blockIdx.x * 256 + tid;
    const u64* ws64 = (const u64*)Ws;
    const u64* ps64 = (const u64*)Ps;
    u64 acc[32], pacc[16];
#pragma unroll
    for (int p = 0; p < 32; ++p) acc[p] = pk2(bs[2 * p], bs[2 * p + 1]);
#pragma unroll
    for (int p = 0; p < 16; ++p) pacc[p] = 0ull;

#pragma unroll 2
    for (int c = 0; c < 64; ++c) {
        float xv = x[c * N3 + v];
        u64 xd = pk2(xv, xv);
#pragma unroll
        for (int p = 0; p < 32; ++p) acc[p] = ffma2(xd, ws64[c * 32 + p], acc[p]);
#pragma unroll
        for (int p = 0; p < 16; ++p) pacc[p] = ffma2(xd, ps64[c * 16 + p], pacc[p]);
    }
#pragma unroll
    for (int p = 0; p < 16; ++p) g_p2[p * N3 + v] = pacc[p];

    float vals[64];
#pragma unroll
    for (int p = 0; p < 32; ++p) upk2(acc[p], vals[2 * p], vals[2 * p + 1]);
    uint4* xh4 = (uint4*)g_xh;
    uint4* xl4 = (uint4*)g_xl;
#pragma unroll
    for (int i = 0; i < 8; ++i) {
        unsigned hw[4], lw[4];
#pragma unroll
        for (int j = 0; j < 4; ++j) {
            float a = vals[i * 8 + 2 * j], b = vals[i * 8 + 2 * j + 1];
            float ah = __bfloat162float(__float2bfloat16(a));
            float bh = __bfloat162float(__float2bfloat16(b));
            hw[j] = bfpk(a, b);
            lw[j] = bfpk(a - ah, b - bh);
        }
        xh4[v * 8 + i] = make_uint4(hw[0], hw[1], hw[2], hw[3]);
        xl4[v * 8 + i] = make_uint4(lw[0], lw[1], lw[2], lw[3]);
    }
}

// ---------------------------------------------------------------------------
// Kernel 1w: encode weights -> [t][o pad224][c] bf16 hi/lo, pre-swizzled.
// ---------------------------------------------------------------------------
__global__ __launch_bounds__(256) void k_wprep(const float* __restrict__ We) {
    int id = blockIdx.x * 256 + threadIdx.x;   // 27*216*64 = 373248
    int t = id / 13824;
    int r = id - t * 13824;
    int o = r >> 6, c = r & 63;
    float v = We[o * 1728 + c * 27 + t];
    __nv_bfloat16 h = __float2bfloat16(v);
    float rf = v - __bfloat162float(h);
    int ci = c >> 3, j = c & 7;
    int dst = t * 14336 + o * 64 + ((ci ^ (o & 7)) << 3) + j;
    g_wbh[dst] = h;
    g_wbl[dst] = __float2bfloat16(rf);
}

// ---------------------------------------------------------------------------
// Kernel 2: encode conv as mma.sync bf16x3 GEMM.
// CTA: M=128 voxels, N=216(+8 pad), K = 27 taps x 64c.  512 threads, 16 warps
// in 8(m) x 2(n) layout: warp = m16 rows x 14 n-tiles (group1: 13 stored).
// B fragments via ldmatrix.x4 over n-tile pairs.  Double-buffered stages.
// ---------------------------------------------------------------------------
#define A_TILE 16384                 // 128 rows x 128 B (one of hi/lo)
#define B_OFF  32768
#define B_TILE 28672                 // 224 rows x 128 B
#define STG_SZ 90112                 // Ah Al Bh Bl

__device__ __forceinline__ void build_stage(uint32_t stage, int t, int tid,
                                            int d, int h0) {
    const char* srcH = (const char*)g_wbh + t * B_TILE;
    const char* srcL = (const char*)g_wbl + t * B_TILE;
    for (int i = tid; i < 1792; i += 512) {
        cp16(stage + B_OFF + i * 16, srcH + i * 16);
        cp16(stage + B_OFF + B_TILE + i * 16, srcL + i * 16);
    }
    int kd = t / 9; int rr = t - kd * 9; int kh = rr / 3; int kw = rr - kh * 3;
    const uint4* xh4 = (const uint4*)g_xh;
    const uint4* xl4 = (const uint4*)g_xl;
#pragma unroll
    for (int it = 0; it < 2; ++it) {
        int idx = tid + it * 512;            // 0..1023: row m (7b) x chunk ci (3b)
        int m = idx >> 3, ci = idx & 7;
        int hr = m >> 5, w = m & 31;
        int dd = d + kd - 1, hh = h0 + hr + kh - 1, ww = w + kw - 1;
        uint4 vh = make_uint4(0, 0, 0, 0), vl = vh;
        if ((unsigned)dd < 32u && (unsigned)hh < 32u && (unsigned)ww < 32u) {
            int v = dd * 1024 + hh * 32 + ww;
            vh = xh4[v * 8 + ci];
            vl = xl4[v * 8 + ci];
        }
        uint32_t dst = stage + m * 128 + ((ci ^ (m & 7)) << 4);
        asm volatile("st.shared.v4.b32 [%0], {%1,%2,%3,%4};" :: "r"(dst),
                     "r"(vh.x), "r"(vh.y), "r"(vh.z), "r"(vh.w) : "memory");
        asm volatile("st.shared.v4.b32 [%0], {%1,%2,%3,%4};" :: "r"(dst + A_TILE),
                     "r"(vl.x), "r"(vl.y), "r"(vl.z), "r"(vl.w) : "memory");
    }
    asm volatile("cp.async.commit_group;" ::: "memory");
}

__global__ __launch_bounds__(512, 1) void k_encode_mma(const float* __restrict__ be) {
    extern __shared__ char dsraw[];
    char* dsm = (char*)(((uintptr_t)dsraw + 1023) & ~(uintptr_t)1023);
    uint32_t s_base = (uint32_t)__cvta_generic_to_shared(dsm);
    __shared__ float bias[216];

    int tid = threadIdx.x;
    int wid = tid >> 5, lane = tid & 31;
    int wm = wid & 7, wn = wid >> 3;     // m-warp (16 rows), n-group (14 tiles)
    int b = blockIdx.x;
    int d = b >> 3, h0 = (b & 7) << 2;

    for (int i = tid; i < 216; i += 512) bias[i] = be[i];

    // per-lane ldmatrix address components
    int ar   = wm * 16 + (lane & 15);    // A tile row
    int akh  = lane >> 4;                // A k-half
    int axor = ar & 7;
    int nr   = lane & 7;                 // B row within n-tile
    int bkh  = (lane >> 3) & 1;          // B k-half
    int tsel = lane >> 4;                // B tile-within-pair
    // lane-constant part of B address (per stage add: B_OFF handled here)
    uint32_t bconst = B_OFF + (uint32_t)(wn * 14 + tsel) * 1024 + nr * 128;

    float acc[56];
#pragma unroll
    for (int i = 0; i < 56; ++i) acc[i] = 0.f;

    build_stage(s_base, 0, tid, d, h0);
    asm volatile("cp.async.wait_group 0;" ::: "memory");
    __syncthreads();

    for (int t = 0; t < 27; ++t) {
        int s = t & 1;
        if (t + 1 < 27) build_stage(s_base + (s ^ 1) * STG_SZ, t + 1, tid, d, h0);

        uint32_t stage = s_base + s * STG_SZ;
        uint32_t abase = stage + ar * 128;
        uint32_t bbase = stage + bconst;
#pragma unroll 1
        for (int ks = 0; ks < 4; ++ks) {
            uint32_t ah[4], al[4];
            uint32_t aaddr = abase + ((((ks << 1) | akh) ^ axor) << 4);
            ldsm4(ah, aaddr);
            ldsm4(al, aaddr + A_TILE);
            uint32_t bsw = bbase + ((((ks << 1) | bkh) ^ nr) << 4);
#pragma unroll
            for (int np = 0; np < 7; ++np) {
                uint32_t bh[4], bl[4];
                uint32_t baddr = bsw + np * 2048;
                ldsm4(bh, baddr);
                ldsm4(bl, baddr + B_TILE);
                float* a0 = &acc[8 * np];
                float* a1 = &acc[8 * np + 4];
                mma16816(a0, ah, bh);
                mma16816(a1, ah, bh + 2);
                mma16816(a0, ah, bl);
                mma16816(a1, ah, bl + 2);
                mma16816(a0, al, bh);
                mma16816(a1, al, bh + 2);
            }
        }
        if (t + 1 < 27) asm volatile("cp.async.wait_group 0;" ::: "memory");
        __syncthreads();
    }

    // epilogue: c-frag -> g_w2 voxel-major [v][216] with bias, 8B v2 stores
    int g = lane >> 2, tq = lane & 3;
    int vbase = d * 1024 + h0 * 32;
    int r0 = wm * 16 + g;
    int nlim = 14 - wn;                  // group1: skip pad tile
#pragma unroll
    for (int n = 0; n < 14; ++n) {
        if (n >= nlim) break;
        int c0 = (wn * 14 + n) * 8 + 2 * tq;
        float b0v = bias[c0], b1v = bias[c0 + 1];
        *(float2*)&g_w2[(u64)(vbase + r0) * 216 + c0] =
            make_float2(acc[4 * n] + b0v, acc[4 * n + 1] + b1v);
        *(float2*)&g_w2[(u64)(vbase + r0 + 8) * 216 + c0] =
            make_float2(acc[4 * n + 2] + b0v, acc[4 * n + 3] + b1v);
    }
}

// ---------------------------------------------------------------------------
// Kernel 3: fused pixelshuffle + softmax(27) + factored reassembly.
// ---------------------------------------------------------------------------
__global__ __launch_bounds__(256) void k_reassemble(float* __restrict__ out) {
    extern __shared__ char rsm[];
    u64*   ps  = (u64*)rsm;                       // 16*306 u64
    float* w2s = (float*)(rsm + 16 * 306 * 8);    // 32*217 floats

    int tid = threadIdx.x;
    int h = blockIdx.x, d = blockIdx.y;
    int w = tid & 31;
    int off = tid >> 5;
    int pd = off >> 2, qh = (off >> 1) & 1, rw = off & 1;
    int vbase = d * 1024 + h * 32;

    for (int i = tid; i < 6912; i += 256) {
        int vr = i / 216, ch = i - vr * 216;
        w2s[vr * 217 + ch] = g_w2[(u64)vbase * 216 + i];
    }
    for (int i = tid; i < 16 * 306; i += 256) {
        int pp = i / 306; int r = i - pp * 306;
        int kd = r / 102; int r2 = r - kd * 102;
        int kh = r2 / 34; int ii = r2 - kh * 34;
        int dd = min(max(d + kd - 1, 0), 31);
        int hh = min(max(h + kh - 1, 0), 31);
        int ww = min(max(ii - 1, 0), 31);
        ps[i] = g_p2[pp * N3 + dd * 1024 + hh * 32 + ww];
    }
    __syncthreads();

    float sw[27];
    float m = -1e30f;
#pragma unroll
    for (int k = 0; k < 27; ++k) {
        float v = w2s[w * 217 + k * 8 + off];
        sw[k] = v;
        m = fmaxf(m, v);
    }
    float s = 0.f;
#pragma unroll
    for (int k = 0; k < 27; ++k) { sw[k] = __expf(sw[k] - m); s += sw[k]; }
    float inv = 1.f / s;
#pragma unroll
    for (int k = 0; k < 27; ++k) sw[k] *= inv;

    u64 acc[16];
#pragma unroll
    for (int p = 0; p < 16; ++p) acc[p] = 0ull;
#pragma unroll
    for (int kd = 0; kd < 3; ++kd)
#pragma unroll
        for (int kh = 0; kh < 3; ++kh)
#pragma unroll
            for (int kw = 0; kw < 3; ++kw) {
                float sv = sw[(kd * 3 + kh) * 3 + kw];
                u64 sd = pk2(sv, sv);
                int base = kd * 102 + kh * 34 + w + kw;
#pragma unroll
                for (int p = 0; p < 16; ++p)
                    acc[p] = ffma2(sd, ps[p * 306 + base], acc[p]);
            }

    int d2 = 2 * d + pd, h2 = 2 * h + qh, w2 = 2 * w + rw;
    int fbase = d2 * 4096 + h2 * 64 + w2;
#pragma unroll
    for (int p = 0; p < 16; ++p) {
        float a, bb; upk2(acc[p], a, bb);
        out[(2 * p) * NF + fbase]     = a;
        out[(2 * p + 1) * NF + fbase] = bb;
    }
}

// ---------------------------------------------------------------------------
extern "C" void kernel_launch(void* const* d_in, const int* in_sizes, int n_in,
                              void* d_out, int out_size) {
    const float* x  = (const float*)d_in[0];
    const float* wc = (const float*)d_in[1];
    const float* bc = (const float*)d_in[2];
    const float* we = (const float*)d_in[3];
    const float* be = (const float*)d_in[4];
    const float* wp = (const float*)d_in[5];
    float* out = (float*)d_out;

    const int enc_smem = 2 * STG_SZ + 1024;             // 181248
    const int rea_smem = 16 * 306 * 8 + 32 * 217 * 4;   // 66944
    static int smem_set = 0;
    if (!smem_set) {
        cudaFuncSetAttribute(k_encode_mma, cudaFuncAttributeMaxDynamicSharedMemorySize,
                             enc_smem);
        cudaFuncSetAttribute(k_reassemble, cudaFuncAttributeMaxDynamicSharedMemorySize,
                             rea_smem);
        smem_set = 1;
    }

    k_front<<<128, 256>>>(x, wc, bc, wp);
    k_wprep<<<1458, 256>>>(we);
    k_encode_mma<<<256, 512, enc_smem>>>(be);
    k_reassemble<<<dim3(32, 32), 256, rea_smem>>>(out);
}

// round 7
// speedup vs baseline: 2.3739x; 1.0134x over previous
#include <cuda_runtime.h>
#include <cuda_bf16.h>
#include <stdint.h>

// CARAFE3d: B=1, C=64, D=H=W=32, c_mid=64, s=2, k=3, out_ch=32
#define N3 32768      // 32^3 coarse voxels
#define NF 262144     // 64^3 fine voxels

typedef unsigned long long u64;

// ---------------- global scratch ----------------
__device__ __align__(16) __nv_bfloat16 g_xh[N3 * 64];        // compressed feats hi, [v][c]
__device__ __align__(16) __nv_bfloat16 g_xl[N3 * 64];        // residual lo,        [v][c]
__device__ __align__(16) __nv_bfloat16 g_wbh[27 * 224 * 64]; // weights hi [t][o(pad224)][c], pre-swizzled
__device__ __align__(16) __nv_bfloat16 g_wbl[27 * 224 * 64]; // weights lo (pad rows stay zero)
__device__ float g_w2[N3 * 216];                             // encode output, voxel-major [v][ch]
__device__ u64   g_p2[16 * N3];                              // projected x, oc-pairs

// ---------------- helpers ----------------
__device__ __forceinline__ u64 pk2(float lo, float hi) {
    u64 r; asm("mov.b64 %0, {%1, %2};" : "=l"(r) : "f"(lo), "f"(hi)); return r;
}
__device__ __forceinline__ void upk2(u64 v, float& lo, float& hi) {
    asm("mov.b64 {%0, %1}, %2;" : "=f"(lo), "=f"(hi) : "l"(v));
}
__device__ __forceinline__ u64 ffma2(u64 a, u64 b, u64 c) {
    u64 d; asm("fma.rn.f32x2 %0, %1, %2, %3;" : "=l"(d) : "l"(a), "l"(b), "l"(c));
    return d;
}
__device__ __forceinline__ unsigned bfpk(float lo, float hi) {  // mem order: lo first
    unsigned r; asm("cvt.rn.bf16x2.f32 %0, %1, %2;" : "=r"(r) : "f"(hi), "f"(lo));
    return r;
}
__device__ __forceinline__ void cp16(uint32_t dst, const void* src) {
    asm volatile("cp.async.ca.shared.global [%0], [%1], 16;" :: "r"(dst), "l"(src));
}
__device__ __forceinline__ void ldsm4(uint32_t* r, uint32_t addr) {
    asm volatile("ldmatrix.sync.aligned.m8n8.x4.shared.b16 {%0,%1,%2,%3}, [%4];"
                 : "=r"(r[0]), "=r"(r[1]), "=r"(r[2]), "=r"(r[3]) : "r"(addr));
}
__device__ __forceinline__ void mma16816(float* c, const uint32_t* a, const uint32_t* b) {
    asm volatile("mma.sync.aligned.m16n8k16.row.col.f32.bf16.bf16.f32 "
                 "{%0,%1,%2,%3}, {%4,%5,%6,%7}, {%8,%9}, {%0,%1,%2,%3};"
                 : "+f"(c[0]), "+f"(c[1]), "+f"(c[2]), "+f"(c[3])
                 : "r"(a[0]), "r"(a[1]), "r"(a[2]), "r"(a[3]), "r"(b[0]), "r"(b[1]));
}

// ---------------------------------------------------------------------------
// Kernel 1: fused 1x1x1 compress (-> bf16 hi/lo, voxel-major) + 1x1x1 proj
// ---------------------------------------------------------------------------
__global__ __launch_bounds__(256) void k_front(const float* __restrict__ x,
                                               const float* __restrict__ Wc,
                                               const float* __restrict__ bc,
                                               const float* __restrict__ Wp) {
    __shared__ __align__(16) float Ws[64 * 64];   // compress [c][cm]
    __shared__ __align__(16) float Ps[64 * 32];   // proj     [c][oc]
    __shared__ float bs[64];
    int tid = threadIdx.x;
    for (int i = tid; i < 4096; i += 256) {
        int c = i >> 6, cm = i & 63;
        Ws[i] = Wc[cm * 64 + c];
    }
    for (int i = tid; i < 2048; i += 256) {
        int c = i >> 5, oc = i & 31;
        Ps[i] = Wp[oc * 64 + c];
    }
    if (tid < 64) bs[tid] = bc[tid];
    __syncthreads();

    int v = blockIdx.x * 256 + tid;
    const u64* ws64 = (const u64*)Ws;
    const u64* ps64 = (const u64*)Ps;
    u64 acc[32], pacc[16];
#pragma unroll
    for (int p = 0; p < 32; ++p) acc[p] = pk2(bs[2 * p], bs[2 * p + 1]);
#pragma unroll
    for (int p = 0; p < 16; ++p) pacc[p] = 0ull;

#pragma unroll 2
    for (int c = 0; c < 64; ++c) {
        float xv = x[c * N3 + v];
        u64 xd = pk2(xv, xv);
#pragma unroll
        for (int p = 0; p < 32; ++p) acc[p] = ffma2(xd, ws64[c * 32 + p], acc[p]);
#pragma unroll
        for (int p = 0; p < 16; ++p) pacc[p] = ffma2(xd, ps64[c * 16 + p], pacc[p]);
    }
#pragma unroll
    for (int p = 0; p < 16; ++p) g_p2[p * N3 + v] = pacc[p];

    float vals[64];
#pragma unroll
    for (int p = 0; p < 32; ++p) upk2(acc[p], vals[2 * p], vals[2 * p + 1]);
    uint4* xh4 = (uint4*)g_xh;
    uint4* xl4 = (uint4*)g_xl;
#pragma unroll
    for (int i = 0; i < 8; ++i) {
        unsigned hw[4], lw[4];
#pragma unroll
        for (int j = 0; j < 4; ++j) {
            float a = vals[i * 8 + 2 * j], b = vals[i * 8 + 2 * j + 1];
            float ah = __bfloat162float(__float2bfloat16(a));
            float bh = __bfloat162float(__float2bfloat16(b));
            hw[j] = bfpk(a, b);
            lw[j] = bfpk(a - ah, b - bh);
        }
        xh4[v * 8 + i] = make_uint4(hw[0], hw[1], hw[2], hw[3]);
        xl4[v * 8 + i] = make_uint4(lw[0], lw[1], lw[2], lw[3]);
    }
}

// ---------------------------------------------------------------------------
// Kernel 1w: encode weights -> [t][o pad224][c] bf16 hi/lo, pre-swizzled.
// ---------------------------------------------------------------------------
__global__ __launch_bounds__(256) void k_wprep(const float* __restrict__ We) {
    int id = blockIdx.x * 256 + threadIdx.x;   // 27*216*64 = 373248
    int t = id / 13824;
    int r = id - t * 13824;
    int o = r >> 6, c = r & 63;
    float v = We[o * 1728 + c * 27 + t];
    __nv_bfloat16 h = __float2bfloat16(v);
    float rf = v - __bfloat162float(h);
    int ci = c >> 3, j = c & 7;
    int dst = t * 14336 + o * 64 + ((ci ^ (o & 7)) << 3) + j;
    g_wbh[dst] = h;
    g_wbl[dst] = __float2bfloat16(rf);
}

// ---------------------------------------------------------------------------
// Kernel 2: encode conv as mma.sync bf16x3 GEMM.
// CTA: M=128 voxels, N=216(+8 pad), K = 27 taps x 64c.  256 threads, 8 warps
// in 4(m) x 2(n): warp tile = m32 x n112 (2 A m-tiles x 14 B n-tiles).
// Register-blocked over m: each B fragment feeds 2 m-tiles -> B smem traffic
// halved vs r5.  acc = 112 f32/thread.  Double-buffered stages.
// ---------------------------------------------------------------------------
#define A_TILE 16384                 // 128 rows x 128 B (one of hi/lo)
#define B_OFF  32768
#define B_TILE 28672                 // 224 rows x 128 B
#define STG_SZ 90112                 // Ah Al Bh Bl

__device__ __forceinline__ void build_stage(uint32_t stage, int t, int tid,
                                            int d, int h0) {
    const char* srcH = (const char*)g_wbh + t * B_TILE;
    const char* srcL = (const char*)g_wbl + t * B_TILE;
    for (int i = tid; i < 1792; i += 256) {
        cp16(stage + B_OFF + i * 16, srcH + i * 16);
        cp16(stage + B_OFF + B_TILE + i * 16, srcL + i * 16);
    }
    int kd = t / 9; int rr = t - kd * 9; int kh = rr / 3; int kw = rr - kh * 3;
    const uint4* xh4 = (const uint4*)g_xh;
    const uint4* xl4 = (const uint4*)g_xl;
#pragma unroll
    for (int it = 0; it < 4; ++it) {
        int idx = tid + it * 256;            // 0..1023: row m (7b) x chunk ci (3b)
        int m = idx >> 3, ci = idx & 7;
        int hr = m >> 5, w = m & 31;
        int dd = d + kd - 1, hh = h0 + hr + kh - 1, ww = w + kw - 1;
        uint4 vh = make_uint4(0, 0, 0, 0), vl = vh;
        if ((unsigned)dd < 32u && (unsigned)hh < 32u && (unsigned)ww < 32u) {
            int v = dd * 1024 + hh * 32 + ww;
            vh = xh4[v * 8 + ci];
            vl = xl4[v * 8 + ci];
        }
        uint32_t dst = stage + m * 128 + ((ci ^ (m & 7)) << 4);
        asm volatile("st.shared.v4.b32 [%0], {%1,%2,%3,%4};" :: "r"(dst),
                     "r"(vh.x), "r"(vh.y), "r"(vh.z), "r"(vh.w) : "memory");
        asm volatile("st.shared.v4.b32 [%0], {%1,%2,%3,%4};" :: "r"(dst + A_TILE),
                     "r"(vl.x), "r"(vl.y), "r"(vl.z), "r"(vl.w) : "memory");
    }
    asm volatile("cp.async.commit_group;" ::: "memory");
}

__global__ __launch_bounds__(256, 1) void k_encode_mma(const float* __restrict__ be) {
    extern __shared__ char dsraw[];
    char* dsm = (char*)(((uintptr_t)dsraw + 1023) & ~(uintptr_t)1023);
    uint32_t s_base = (uint32_t)__cvta_generic_to_shared(dsm);
    __shared__ float bias[216];

    int tid = threadIdx.x;
    int wid = tid >> 5, lane = tid & 31;
    int wm = wid & 3, wn = wid >> 2;     // m-warp (32 rows), n-group (14 tiles)
    int b = blockIdx.x;
    int d = b >> 3, h0 = (b & 7) << 2;

    for (int i = tid; i < 216; i += 256) bias[i] = be[i];

    // per-lane ldmatrix address components
    int ar   = wm * 32 + (lane & 15);    // A tile row (m-tile 0; tile 1 = +16)
    int akh  = lane >> 4;                // A k-half
    int axor = ar & 7;                   // same for ar+16
    int nr   = lane & 7;                 // B row within n-tile
    int bkh  = (lane >> 3) & 1;          // B k-half
    int tsel = lane >> 4;                // B tile-within-pair
    uint32_t bconst = B_OFF + (uint32_t)(wn * 14 + tsel) * 1024 + nr * 128;

    float acc[112];                      // [np(7)][ntile(2)][mtile(2)][4]
#pragma unroll
    for (int i = 0; i < 112; ++i) acc[i] = 0.f;

    build_stage(s_base, 0, tid, d, h0);
    asm volatile("cp.async.wait_group 0;" ::: "memory");
    __syncthreads();

    for (int t = 0; t < 27; ++t) {
        int s = t & 1;
        if (t + 1 < 27) build_stage(s_base + (s ^ 1) * STG_SZ, t + 1, tid, d, h0);

        uint32_t stage = s_base + s * STG_SZ;
        uint32_t abase = stage + ar * 128;
        uint32_t bbase = stage + bconst;
#pragma unroll 1
        for (int ks = 0; ks < 4; ++ks) {
            uint32_t ah0[4], ah1[4], al0[4], al1[4];
            uint32_t aaddr = abase + ((((ks << 1) | akh) ^ axor) << 4);
            ldsm4(ah0, aaddr);
            ldsm4(ah1, aaddr + 16 * 128);
            ldsm4(al0, aaddr + A_TILE);
            ldsm4(al1, aaddr + A_TILE + 16 * 128);
            uint32_t bsw = bbase + ((((ks << 1) | bkh) ^ nr) << 4);
#pragma unroll
            for (int np = 0; np < 7; ++np) {
                uint32_t bh[4], bl[4];
                uint32_t baddr = bsw + np * 2048;
                ldsm4(bh, baddr);
                ldsm4(bl, baddr + B_TILE);
                float* c00 = &acc[16 * np];       // ntile0, mtile0
                float* c01 = &acc[16 * np + 4];   // ntile0, mtile1
                float* c10 = &acc[16 * np + 8];   // ntile1, mtile0
                float* c11 = &acc[16 * np + 12];  // ntile1, mtile1
                mma16816(c00, ah0, bh);
                mma16816(c01, ah1, bh);
                mma16816(c10, ah0, bh + 2);
                mma16816(c11, ah1, bh + 2);
                mma16816(c00, ah0, bl);
                mma16816(c01, ah1, bl);
                mma16816(c10, ah0, bl + 2);
                mma16816(c11, ah1, bl + 2);
                mma16816(c00, al0, bh);
                mma16816(c01, al1, bh);
                mma16816(c10, al0, bh + 2);
                mma16816(c11, al1, bh + 2);
            }
        }
        if (t + 1 < 27) asm volatile("cp.async.wait_group 0;" ::: "memory");
        __syncthreads();
    }

    // epilogue: c-frag -> g_w2 voxel-major [v][216] with bias, 8B v2 stores
    // group wn owns n-subtiles (wn*14 + 0 .. 13); GLOBAL tile 27 is pad, so
    // group 1 keeps only subtiles 0..12:  nlim = 13 - wn.  (r6 bug: bound was
    // computed in the wrong index space and never fired -> OOB row writes.)
    int g = lane >> 2, tq = lane & 3;
    int vbase = d * 1024 + h0 * 32;
    int r0 = wm * 32 + g;
    int nlim = 13 - wn;
#pragma unroll
    for (int np = 0; np < 7; ++np) {
#pragma unroll
        for (int nt = 0; nt < 2; ++nt) {
            if (2 * np + nt > nlim) break;
            int c0 = (wn * 14 + 2 * np + nt) * 8 + 2 * tq;
            float b0v = bias[c0], b1v = bias[c0 + 1];
            const float* c0p = &acc[16 * np + 8 * nt];
            *(float2*)&g_w2[(u64)(vbase + r0) * 216 + c0] =
                make_float2(c0p[0] + b0v, c0p[1] + b1v);
            *(float2*)&g_w2[(u64)(vbase + r0 + 8) * 216 + c0] =
                make_float2(c0p[2] + b0v, c0p[3] + b1v);
            *(float2*)&g_w2[(u64)(vbase + r0 + 16) * 216 + c0] =
                make_float2(c0p[4] + b0v, c0p[5] + b1v);
            *(float2*)&g_w2[(u64)(vbase + r0 + 24) * 216 + c0] =
                make_float2(c0p[6] + b0v, c0p[7] + b1v);
        }
    }
}

// ---------------------------------------------------------------------------
// Kernel 3: fused pixelshuffle + softmax(27) + factored reassembly.
// ---------------------------------------------------------------------------
__global__ __launch_bounds__(256) void k_reassemble(float* __restrict__ out) {
    extern __shared__ char rsm[];
    u64*   ps  = (u64*)rsm;                       // 16*306 u64
    float* w2s = (float*)(rsm + 16 * 306 * 8);    // 32*217 floats

    int tid = threadIdx.x;
    int h = blockIdx.x, d = blockIdx.y;
    int w = tid & 31;
    int off = tid >> 5;
    int pd = off >> 2, qh = (off >> 1) & 1, rw = off & 1;
    int vbase = d * 1024 + h * 32;

    for (int i = tid; i < 6912; i += 256) {
        int vr = i / 216, ch = i - vr * 216;
        w2s[vr * 217 + ch] = g_w2[(u64)vbase * 216 + i];
    }
    for (int i = tid; i < 16 * 306; i += 256) {
        int pp = i / 306; int r = i - pp * 306;
        int kd = r / 102; int r2 = r - kd * 102;
        int kh = r2 / 34; int ii = r2 - kh * 34;
        int dd = min(max(d + kd - 1, 0), 31);
        int hh = min(max(h + kh - 1, 0), 31);
        int ww = min(max(ii - 1, 0), 31);
        ps[i] = g_p2[pp * N3 + dd * 1024 + hh * 32 + ww];
    }
    __syncthreads();

    float sw[27];
    float m = -1e30f;
#pragma unroll
    for (int k = 0; k < 27; ++k) {
        float v = w2s[w * 217 + k * 8 + off];
        sw[k] = v;
        m = fmaxf(m, v);
    }
    float s = 0.f;
#pragma unroll
    for (int k = 0; k < 27; ++k) { sw[k] = __expf(sw[k] - m); s += sw[k]; }
    float inv = 1.f / s;
#pragma unroll
    for (int k = 0; k < 27; ++k) sw[k] *= inv;

    u64 acc[16];
#pragma unroll
    for (int p = 0; p < 16; ++p) acc[p] = 0ull;
#pragma unroll
    for (int kd = 0; kd < 3; ++kd)
#pragma unroll
        for (int kh = 0; kh < 3; ++kh)
#pragma unroll
            for (int kw = 0; kw < 3; ++kw) {
                float sv = sw[(kd * 3 + kh) * 3 + kw];
                u64 sd = pk2(sv, sv);
                int base = kd * 102 + kh * 34 + w + kw;
#pragma unroll
                for (int p = 0; p < 16; ++p)
                    acc[p] = ffma2(sd, ps[p * 306 + base], acc[p]);
            }

    int d2 = 2 * d + pd, h2 = 2 * h + qh, w2 = 2 * w + rw;
    int fbase = d2 * 4096 + h2 * 64 + w2;
#pragma unroll
    for (int p = 0; p < 16; ++p) {
        float a, bb; upk2(acc[p], a, bb);
        out[(2 * p) * NF + fbase]     = a;
        out[(2 * p + 1) * NF + fbase] = bb;
    }
}

// ---------------------------------------------------------------------------
extern "C" void kernel_launch(void* const* d_in, const int* in_sizes, int n_in,
                              void* d_out, int out_size) {
    const float* x  = (const float*)d_in[0];
    const float* wc = (const float*)d_in[1];
    const float* bc = (const float*)d_in[2];
    const float* we = (const float*)d_in[3];
    const float* be = (const float*)d_in[4];
    const float* wp = (const float*)d_in[5];
    float* out = (float*)d_out;

    const int enc_smem = 2 * STG_SZ + 1024;             // 181248
    const int rea_smem = 16 * 306 * 8 + 32 * 217 * 4;   // 66944
    static int smem_set = 0;
    if (!smem_set) {
        cudaFuncSetAttribute(k_encode_mma, cudaFuncAttributeMaxDynamicSharedMemorySize,
                             enc_smem);
        cudaFuncSetAttribute(k_reassemble, cudaFuncAttributeMaxDynamicSharedMemorySize,
                             rea_smem);
        smem_set = 1;
    }

    k_front<<<128, 256>>>(x, wc, bc, wp);
    k_wprep<<<1458, 256>>>(we);
    k_encode_mma<<<256, 256, enc_smem>>>(be);
    k_reassemble<<<dim3(32, 32), 256, rea_smem>>>(out);
}

// round 8
// speedup vs baseline: 4.5196x; 1.9039x over previous
#include <cuda_runtime.h>
#include <cuda_fp16.h>
#include <stdint.h>

// CARAFE3d: B=1, C=64, D=H=W=32, c_mid=64, s=2, k=3, out_ch=32
#define N3 32768      // 32^3 coarse voxels
#define NF 262144     // 64^3 fine voxels

typedef unsigned long long u64;

// ---------------- global scratch ----------------
__device__ __align__(16) __half g_xf[N3 * 64];         // compressed feats fp16, [v][c]
__device__ __align__(16) __half g_wf[27 * 224 * 64];   // weights fp16 [t][o pad224][c], pre-swizzled
__device__ float g_w2[N3 * 216];                       // encode output, voxel-major [v][ch]
__device__ u64   g_p2[16 * N3];                        // projected x, oc-pairs

// ---------------- helpers ----------------
__device__ __forceinline__ u64 pk2(float lo, float hi) {
    u64 r; asm("mov.b64 %0, {%1, %2};" : "=l"(r) : "f"(lo), "f"(hi)); return r;
}
__device__ __forceinline__ void upk2(u64 v, float& lo, float& hi) {
    asm("mov.b64 {%0, %1}, %2;" : "=f"(lo), "=f"(hi) : "l"(v));
}
__device__ __forceinline__ u64 ffma2(u64 a, u64 b, u64 c) {
    u64 d; asm("fma.rn.f32x2 %0, %1, %2, %3;" : "=l"(d) : "l"(a), "l"(b), "l"(c));
    return d;
}
__device__ __forceinline__ unsigned hfpk(float lo, float hi) {  // mem order: lo first
    unsigned r; asm("cvt.rn.f16x2.f32 %0, %1, %2;" : "=r"(r) : "f"(hi), "f"(lo));
    return r;
}
__device__ __forceinline__ void cp16(uint32_t dst, const void* src) {
    asm volatile("cp.async.ca.shared.global [%0], [%1], 16;" :: "r"(dst), "l"(src));
}
__device__ __forceinline__ void ldsm4(uint32_t* r, uint32_t addr) {
    asm volatile("ldmatrix.sync.aligned.m8n8.x4.shared.b16 {%0,%1,%2,%3}, [%4];"
                 : "=r"(r[0]), "=r"(r[1]), "=r"(r[2]), "=r"(r[3]) : "r"(addr));
}
__device__ __forceinline__ void ldsm2(uint32_t* r, uint32_t addr) {
    asm volatile("ldmatrix.sync.aligned.m8n8.x2.shared.b16 {%0,%1}, [%2];"
                 : "=r"(r[0]), "=r"(r[1]) : "r"(addr));
}
__device__ __forceinline__ void mma16816(float* c, const uint32_t* a, const uint32_t* b) {
    asm volatile("mma.sync.aligned.m16n8k16.row.col.f32.f16.f16.f32 "
                 "{%0,%1,%2,%3}, {%4,%5,%6,%7}, {%8,%9}, {%0,%1,%2,%3};"
                 : "+f"(c[0]), "+f"(c[1]), "+f"(c[2]), "+f"(c[3])
                 : "r"(a[0]), "r"(a[1]), "r"(a[2]), "r"(a[3]), "r"(b[0]), "r"(b[1]));
}

// ---------------------------------------------------------------------------
// Kernel 1: fused 1x1x1 compress (-> fp16 voxel-major) + 1x1x1 projection
// ---------------------------------------------------------------------------
__global__ __launch_bounds__(256) void k_front(const float* __restrict__ x,
                                               const float* __restrict__ Wc,
                                               const float* __restrict__ bc,
                                               const float* __restrict__ Wp) {
    __shared__ __align__(16) float Ws[64 * 64];   // compress [c][cm]
    __shared__ __align__(16) float Ps[64 * 32];   // proj     [c][oc]
    __shared__ float bs[64];
    int tid = threadIdx.x;
    for (int i = tid; i < 4096; i += 256) {
        int c = i >> 6, cm = i & 63;
        Ws[i] = Wc[cm * 64 + c];
    }
    for (int i = tid; i < 2048; i += 256) {
        int c = i >> 5, oc = i & 31;
        Ps[i] = Wp[oc * 64 + c];
    }
    if (tid < 64) bs[tid] = bc[tid];
    __syncthreads();

    int v = blockIdx.x * 256 + tid;
    const u64* ws64 = (const u64*)Ws;
    const u64* ps64 = (const u64*)Ps;
    u64 acc[32], pacc[16];
#pragma unroll
    for (int p = 0; p < 32; ++p) acc[p] = pk2(bs[2 * p], bs[2 * p + 1]);
#pragma unroll
    for (int p = 0; p < 16; ++p) pacc[p] = 0ull;

#pragma unroll 2
    for (int c = 0; c < 64; ++c) {
        float xv = x[c * N3 + v];
        u64 xd = pk2(xv, xv);
#pragma unroll
        for (int p = 0; p < 32; ++p) acc[p] = ffma2(xd, ws64[c * 32 + p], acc[p]);
#pragma unroll
        for (int p = 0; p < 16; ++p) pacc[p] = ffma2(xd, ps64[c * 16 + p], pacc[p]);
    }
#pragma unroll
    for (int p = 0; p < 16; ++p) g_p2[p * N3 + v] = pacc[p];

    float vals[64];
#pragma unroll
    for (int p = 0; p < 32; ++p) upk2(acc[p], vals[2 * p], vals[2 * p + 1]);
    uint4* xf4 = (uint4*)g_xf;
#pragma unroll
    for (int i = 0; i < 8; ++i) {
        unsigned hw[4];
#pragma unroll
        for (int j = 0; j < 4; ++j)
            hw[j] = hfpk(vals[i * 8 + 2 * j], vals[i * 8 + 2 * j + 1]);
        xf4[v * 8 + i] = make_uint4(hw[0], hw[1], hw[2], hw[3]);
    }
}

// ---------------------------------------------------------------------------
// Kernel 1w: encode weights -> [t][o pad224][c] fp16, pre-swizzled (SW128)
// so a linear copy into smem lands in ldmatrix layout. chunk ci -> ci^(o&7).
// Pad rows (216..223) stay zero from static init.
// ---------------------------------------------------------------------------
__global__ __launch_bounds__(256) void k_wprep(const float* __restrict__ We) {
    int id = blockIdx.x * 256 + threadIdx.x;   // 27*216*64 = 373248
    int t = id / 13824;
    int r = id - t * 13824;
    int o = r >> 6, c = r & 63;
    float v = We[o * 1728 + c * 27 + t];
    int ci = c >> 3, j = c & 7;
    int dst = t * 14336 + o * 64 + ((ci ^ (o & 7)) << 3) + j;
    g_wf[dst] = __float2half(v);
}

// ---------------------------------------------------------------------------
// Kernel 2: encode conv as SINGLE-PASS fp16 mma.sync GEMM (3x fewer MMAs
// than the bf16x3 split; fp16's 11-bit mantissa keeps rel err ~1.5e-4).
// CTA: M=128 voxels, N=216(+8 pad), K = 27 taps x 64c.  256 threads, 8 warps
// in 2(m) x 4(n): warp tile = m64 x n56 (4 A m-tiles x 7 B n-subtiles).
// acc = 112 f32/thread.  Double-buffered 44KB stages.
// ---------------------------------------------------------------------------
#define A_TILE 16384                 // 128 rows x 128 B
#define B_TILE 28672                 // 224 rows x 128 B
#define STG_SZ 45056                 // A then B

__device__ __forceinline__ void build_stage(uint32_t stage, int t, int tid,
                                            int d, int h0) {
    const char* srcB = (const char*)g_wf + t * B_TILE;
    for (int i = tid; i < 1792; i += 256)
        cp16(stage + A_TILE + i * 16, srcB + i * 16);
    int kd = t / 9; int rr = t - kd * 9; int kh = rr / 3; int kw = rr - kh * 3;
    const uint4* xf4 = (const uint4*)g_xf;
#pragma unroll
    for (int it = 0; it < 4; ++it) {
        int idx = tid + it * 256;            // 0..1023: row m (7b) x chunk ci (3b)
        int m = idx >> 3, ci = idx & 7;
        int hr = m >> 5, w = m & 31;
        int dd = d + kd - 1, hh = h0 + hr + kh - 1, ww = w + kw - 1;
        uint4 vh = make_uint4(0, 0, 0, 0);
        if ((unsigned)dd < 32u && (unsigned)hh < 32u && (unsigned)ww < 32u) {
            int v = dd * 1024 + hh * 32 + ww;
            vh = xf4[v * 8 + ci];
        }
        uint32_t dst = stage + m * 128 + ((ci ^ (m & 7)) << 4);
        asm volatile("st.shared.v4.b32 [%0], {%1,%2,%3,%4};" :: "r"(dst),
                     "r"(vh.x), "r"(vh.y), "r"(vh.z), "r"(vh.w) : "memory");
    }
    asm volatile("cp.async.commit_group;" ::: "memory");
}

__global__ __launch_bounds__(256, 1) void k_encode_mma(const float* __restrict__ be) {
    extern __shared__ char dsraw[];
    char* dsm = (char*)(((uintptr_t)dsraw + 1023) & ~(uintptr_t)1023);
    uint32_t s_base = (uint32_t)__cvta_generic_to_shared(dsm);
    __shared__ float bias[216];

    int tid = threadIdx.x;
    int wid = tid >> 5, lane = tid & 31;
    int wm = wid & 1, wn = wid >> 1;     // m-warp (64 rows), n-group (7 subtiles)
    int b = blockIdx.x;
    int d = b >> 3, h0 = (b & 7) << 2;

    for (int i = tid; i < 216; i += 256) bias[i] = be[i];

    // per-lane ldmatrix address components
    int ar   = wm * 64 + (lane & 15);    // A tile row (m-tiles at +0,+16,+32,+48)
    int akh  = lane >> 4;                // A k-half
    int axor = ar & 7;                   // invariant across +16 m-tiles
    int nr   = lane & 7;                 // B row within n8 subtile
    int bkh  = (lane >> 3) & 1;          // B k-half
    int tsel = lane >> 4;                // B subtile-within-pair
    // B region starts at stage + A_TILE; group base = subtile (wn*7)
    uint32_t bpair0 = A_TILE + (uint32_t)(wn * 7 + tsel) * 1024 + nr * 128;
    uint32_t b6base = A_TILE + (uint32_t)(wn * 7 + 6) * 1024 + nr * 128;

    float acc[112];                      // [subtile j(7)][mtile(4)][4]
#pragma unroll
    for (int i = 0; i < 112; ++i) acc[i] = 0.f;

    build_stage(s_base, 0, tid, d, h0);
    asm volatile("cp.async.wait_group 0;" ::: "memory");
    __syncthreads();

    for (int t = 0; t < 27; ++t) {
        int s = t & 1;
        if (t + 1 < 27) build_stage(s_base + (s ^ 1) * STG_SZ, t + 1, tid, d, h0);

        uint32_t stage = s_base + s * STG_SZ;
        uint32_t abase = stage + ar * 128;
#pragma unroll
        for (int ks = 0; ks < 4; ++ks) {
            uint32_t a[4][4];
            uint32_t aaddr = abase + ((((ks << 1) | akh) ^ axor) << 4);
            ldsm4(a[0], aaddr);
            ldsm4(a[1], aaddr + 16 * 128);
            ldsm4(a[2], aaddr + 32 * 128);
            ldsm4(a[3], aaddr + 48 * 128);

            uint32_t bswz = (((ks << 1) | bkh) ^ nr) << 4;
            uint32_t bp[3][4], b6[2];
#pragma unroll
            for (int jp = 0; jp < 3; ++jp)
                ldsm4(bp[jp], stage + bpair0 + jp * 2048 + bswz);
            ldsm2(b6, stage + b6base + bswz);

#pragma unroll
            for (int jp = 0; jp < 3; ++jp) {
#pragma unroll
                for (int mt = 0; mt < 4; ++mt) {
                    mma16816(&acc[(2 * jp) * 16 + mt * 4], a[mt], bp[jp]);
                    mma16816(&acc[(2 * jp + 1) * 16 + mt * 4], a[mt], bp[jp] + 2);
                }
            }
#pragma unroll
            for (int mt = 0; mt < 4; ++mt)
                mma16816(&acc[96 + mt * 4], a[mt], b6);
        }
        if (t + 1 < 27) asm volatile("cp.async.wait_group 0;" ::: "memory");
        __syncthreads();
    }

    // epilogue: c-frag -> g_w2 voxel-major [v][216] with bias, 8B v2 stores.
    // Global n-subtile = wn*7 + j; subtile 27 (wn==3, j==6) is pad -> skipped.
    int g = lane >> 2, tq = lane & 3;
    int vbase = d * 1024 + h0 * 32;
#pragma unroll
    for (int j = 0; j < 7; ++j) {
        if (wn == 3 && j == 6) break;
        int c0 = (wn * 7 + j) * 8 + 2 * tq;
        float b0v = bias[c0], b1v = bias[c0 + 1];
#pragma unroll
        for (int mt = 0; mt < 4; ++mt) {
            int r = wm * 64 + mt * 16 + g;
            const float* cp = &acc[j * 16 + mt * 4];
            *(float2*)&g_w2[(u64)(vbase + r) * 216 + c0] =
                make_float2(cp[0] + b0v, cp[1] + b1v);
            *(float2*)&g_w2[(u64)(vbase + r + 8) * 216 + c0] =
                make_float2(cp[2] + b0v, cp[3] + b1v);
        }
    }
}

// ---------------------------------------------------------------------------
// Kernel 3: fused pixelshuffle + softmax(27) + factored reassembly.
// Lane map: off FAST (tid&7) so the 8 fine-offset threads of one coarse voxel
// share a warp -> LDS broadcast for the tap reads (halves LDS wavefronts).
// Softmax logits read direct from voxel-major g_w2 (L2-resident).
// ---------------------------------------------------------------------------
__global__ __launch_bounds__(256) void k_reassemble(float* __restrict__ out) {
    extern __shared__ char rsm[];
    u64* ps = (u64*)rsm;                          // 16*306 u64 (39168 B)

    int tid = threadIdx.x;
    int h = blockIdx.x, d = blockIdx.y;
    int off = tid & 7;                            // pd*4 + qh*2 + rw
    int w = tid >> 3;                             // 0..31
    int pd = off >> 2, qh = (off >> 1) & 1, rw = off & 1;
    int vbase = d * 1024 + h * 32;

    // projected-patch slab (replicate padding)
    for (int i = tid; i < 16 * 306; i += 256) {
        int pp = i / 306; int r = i - pp * 306;
        int kd = r / 102; int r2 = r - kd * 102;
        int kh = r2 / 34; int ii = r2 - kh * 34;
        int dd = min(max(d + kd - 1, 0), 31);
        int hh = min(max(h + kh - 1, 0), 31);
        int ww = min(max(ii - 1, 0), 31);
        ps[i] = g_p2[pp * N3 + dd * 1024 + hh * 32 + ww];
    }
    __syncthreads();

    // softmax over 27 taps: logits at g_w2[v][k*8 + off]
    const float* w2v = &g_w2[(u64)(vbase + w) * 216];
    float sw[27];
    float m = -1e30f;
#pragma unroll
    for (int k = 0; k < 27; ++k) {
        float v = w2v[k * 8 + off];
        sw[k] = v;
        m = fmaxf(m, v);
    }
    float s = 0.f;
#pragma unroll
    for (int k = 0; k < 27; ++k) { sw[k] = __expf(sw[k] - m); s += sw[k]; }
    float inv = 1.f / s;
#pragma unroll
    for (int k = 0; k < 27; ++k) sw[k] *= inv;

    u64 acc[16];
#pragma unroll
    for (int p = 0; p < 16; ++p) acc[p] = 0ull;
#pragma unroll
    for (int kd = 0; kd < 3; ++kd)
#pragma unroll
        for (int kh = 0; kh < 3; ++kh)
#pragma unroll
            for (int kw = 0; kw < 3; ++kw) {
                float sv = sw[(kd * 3 + kh) * 3 + kw];
                u64 sd = pk2(sv, sv);
                int base = kd * 102 + kh * 34 + w + kw;
#pragma unroll
                for (int p = 0; p < 16; ++p)
                    acc[p] = ffma2(sd, ps[p * 306 + base], acc[p]);
            }

    int d2 = 2 * d + pd, h2 = 2 * h + qh, w2 = 2 * w + rw;
    int fbase = d2 * 4096 + h2 * 64 + w2;
#pragma unroll
    for (int p = 0; p < 16; ++p) {
        float a, bb; upk2(acc[p], a, bb);
        out[(2 * p) * NF + fbase]     = a;
        out[(2 * p + 1) * NF + fbase] = bb;
    }
}

// ---------------------------------------------------------------------------
extern "C" void kernel_launch(void* const* d_in, const int* in_sizes, int n_in,
                              void* d_out, int out_size) {
    const float* x  = (const float*)d_in[0];
    const float* wc = (const float*)d_in[1];
    const float* bc = (const float*)d_in[2];
    const float* we = (const float*)d_in[3];
    const float* be = (const float*)d_in[4];
    const float* wp = (const float*)d_in[5];
    float* out = (float*)d_out;

    const int enc_smem = 2 * STG_SZ + 1024;   // 91136
    const int rea_smem = 16 * 306 * 8;        // 39168
    static int smem_set = 0;
    if (!smem_set) {
        cudaFuncSetAttribute(k_encode_mma, cudaFuncAttributeMaxDynamicSharedMemorySize,
                             enc_smem);
        cudaFuncSetAttribute(k_reassemble, cudaFuncAttributeMaxDynamicSharedMemorySize,
                             rea_smem);
        smem_set = 1;
    }

    k_front<<<128, 256>>>(x, wc, bc, wp);
    k_wprep<<<1458, 256>>>(we);
    k_encode_mma<<<256, 256, enc_smem>>>(be);
    k_reassemble<<<dim3(32, 32), 256, rea_smem>>>(out);
}

// round 10
// speedup vs baseline: 4.6517x; 1.0292x over previous
#include <cuda_runtime.h>
#include <cuda_fp16.h>
#include <stdint.h>

// CARAFE3d: B=1, C=64, D=H=W=32, c_mid=64, s=2, k=3, out_ch=32
#define N3 32768      // 32^3 coarse voxels
#define NF 262144     // 64^3 fine voxels

typedef unsigned long long u64;

// ---------------- global scratch ----------------
__device__ __align__(16) __half g_xf[N3 * 64];         // compressed feats fp16, [v][c]
__device__ __align__(16) __half g_wf[27 * 224 * 64];   // weights fp16 [t][o pad224][c], pre-swizzled
__device__ float g_w2[N3 * 216];                       // encode output, voxel-major [v][ch]
__device__ u64   g_p2[16 * N3];                        // projected x, oc-pairs

// ---------------- helpers ----------------
__device__ __forceinline__ u64 pk2(float lo, float hi) {
    u64 r; asm("mov.b64 %0, {%1, %2};" : "=l"(r) : "f"(lo), "f"(hi)); return r;
}
__device__ __forceinline__ void upk2(u64 v, float& lo, float& hi) {
    asm("mov.b64 {%0, %1}, %2;" : "=f"(lo), "=f"(hi) : "l"(v));
}
__device__ __forceinline__ u64 ffma2(u64 a, u64 b, u64 c) {
    u64 d; asm("fma.rn.f32x2 %0, %1, %2, %3;" : "=l"(d) : "l"(a), "l"(b), "l"(c));
    return d;
}
__device__ __forceinline__ unsigned hfpk(float lo, float hi) {  // mem order: lo first
    unsigned r; asm("cvt.rn.f16x2.f32 %0, %1, %2;" : "=r"(r) : "f"(hi), "f"(lo));
    return r;
}
__device__ __forceinline__ void cp16(uint32_t dst, const void* src) {
    asm volatile("cp.async.ca.shared.global [%0], [%1], 16;" :: "r"(dst), "l"(src));
}
// zero-fill variant: src-size 0 -> writes 16B of zeros, reads nothing
__device__ __forceinline__ void cp16z(uint32_t dst, const void* src, int srcsz) {
    asm volatile("cp.async.ca.shared.global [%0], [%1], 16, %2;"
                 :: "r"(dst), "l"(src), "r"(srcsz));
}
__device__ __forceinline__ void ldsm4(uint32_t* r, uint32_t addr) {
    asm volatile("ldmatrix.sync.aligned.m8n8.x4.shared.b16 {%0,%1,%2,%3}, [%4];"
                 : "=r"(r[0]), "=r"(r[1]), "=r"(r[2]), "=r"(r[3]) : "r"(addr));
}
__device__ __forceinline__ void ldsm2(uint32_t* r, uint32_t addr) {
    asm volatile("ldmatrix.sync.aligned.m8n8.x2.shared.b16 {%0,%1}, [%2];"
                 : "=r"(r[0]), "=r"(r[1]) : "r"(addr));
}
__device__ __forceinline__ void mma16816(float* c, const uint32_t* a, const uint32_t* b) {
    asm volatile("mma.sync.aligned.m16n8k16.row.col.f32.f16.f16.f32 "
                 "{%0,%1,%2,%3}, {%4,%5,%6,%7}, {%8,%9}, {%0,%1,%2,%3};"
                 : "+f"(c[0]), "+f"(c[1]), "+f"(c[2]), "+f"(c[3])
                 : "r"(a[0]), "r"(a[1]), "r"(a[2]), "r"(a[3]), "r"(b[0]), "r"(b[1]));
}

// ---------------------------------------------------------------------------
// Kernel 1: MERGED front.
//  blocks [0,128):    fused 1x1x1 compress (-> fp16 voxel-major) + projection
//  blocks [128,1586): encode-weight prep -> [t][o pad224][c] fp16, pre-swizzled
// ---------------------------------------------------------------------------
__global__ __launch_bounds__(256) void k_front(const float* __restrict__ x,
                                               const float* __restrict__ Wc,
                                               const float* __restrict__ bc,
                                               const float* __restrict__ Wp,
                                               const float* __restrict__ We) {
    if (blockIdx.x >= 128) {
        int id = (blockIdx.x - 128) * 256 + threadIdx.x;   // 27*216*64 = 373248
        int t = id / 13824;
        int r = id - t * 13824;
        int o = r >> 6, c = r & 63;
        float v = We[o * 1728 + c * 27 + t];
        int ci = c >> 3, j = c & 7;
        int dst = t * 14336 + o * 64 + ((ci ^ (o & 7)) << 3) + j;
        g_wf[dst] = __float2half(v);
        return;
    }

    __shared__ __align__(16) float Ws[64 * 64];   // compress [c][cm]
    __shared__ __align__(16) float Ps[64 * 32];   // proj     [c][oc]
    __shared__ float bs[64];
    int tid = threadIdx.x;
    for (int i = tid; i < 4096; i += 256) {
        int c = i >> 6, cm = i & 63;
        Ws[i] = Wc[cm * 64 + c];
    }
    for (int i = tid; i < 2048; i += 256) {
        int c = i >> 5, oc = i & 31;
        Ps[i] = Wp[oc * 64 + c];
    }
    if (tid < 64) bs[tid] = bc[tid];
    __syncthreads();

    int v = blockIdx.x * 256 + tid;
    const u64* ws64 = (const u64*)Ws;
    const u64* ps64 = (const u64*)Ps;
    u64 acc[32], pacc[16];
#pragma unroll
    for (int p = 0; p < 32; ++p) acc[p] = pk2(bs[2 * p], bs[2 * p + 1]);
#pragma unroll
    for (int p = 0; p < 16; ++p) pacc[p] = 0ull;

#pragma unroll 2
    for (int c = 0; c < 64; ++c) {
        float xv = x[c * N3 + v];
        u64 xd = pk2(xv, xv);
#pragma unroll
        for (int p = 0; p < 32; ++p) acc[p] = ffma2(xd, ws64[c * 32 + p], acc[p]);
#pragma unroll
        for (int p = 0; p < 16; ++p) pacc[p] = ffma2(xd, ps64[c * 16 + p], pacc[p]);
    }
#pragma unroll
    for (int p = 0; p < 16; ++p) g_p2[p * N3 + v] = pacc[p];

    float vals[64];
#pragma unroll
    for (int p = 0; p < 32; ++p) upk2(acc[p], vals[2 * p], vals[2 * p + 1]);
    uint4* xf4 = (uint4*)g_xf;
#pragma unroll
    for (int i = 0; i < 8; ++i) {
        unsigned hw[4];
#pragma unroll
        for (int j = 0; j < 4; ++j)
            hw[j] = hfpk(vals[i * 8 + 2 * j], vals[i * 8 + 2 * j + 1]);
        xf4[v * 8 + i] = make_uint4(hw[0], hw[1], hw[2], hw[3]);
    }
}

// ---------------------------------------------------------------------------
// Kernel 2: encode conv as single-pass fp16 mma.sync GEMM.
// CTA: M=128 voxels, N=216(+8 pad), K = 27 taps x 64c.  256 threads, 8 warps
// in 2(m) x 4(n): warp tile = m64 x n56.  Double-buffered 44KB stages; the
// ENTIRE stage build (A with zero-fill padding + B) is cp.async.
// ---------------------------------------------------------------------------
#define A_TILE 16384                 // 128 rows x 128 B
#define B_TILE 28672                 // 224 rows x 128 B
#define STG_SZ 45056                 // A then B

__device__ __forceinline__ void build_stage(uint32_t stage, int t, int tid,
                                            int d, int h0) {
    const char* srcB = (const char*)g_wf + t * B_TILE;
    for (int i = tid; i < 1792; i += 256)
        cp16(stage + A_TILE + i * 16, srcB + i * 16);
    int kd = t / 9; int rr = t - kd * 9; int kh = rr / 3; int kw = rr - kh * 3;
    const uint4* xf4 = (const uint4*)g_xf;
#pragma unroll
    for (int it = 0; it < 4; ++it) {
        int idx = tid + it * 256;            // 0..1023: row m (7b) x chunk ci (3b)
        int m = idx >> 3, ci = idx & 7;
        int hr = m >> 5, w = m & 31;
        int dd = d + kd - 1, hh = h0 + hr + kh - 1, ww = w + kw - 1;
        bool ok = (unsigned)dd < 32u && (unsigned)hh < 32u && (unsigned)ww < 32u;
        int v = ok ? (dd * 1024 + hh * 32 + ww) * 8 + ci : 0;
        uint32_t dst = stage + m * 128 + ((ci ^ (m & 7)) << 4);
        cp16z(dst, xf4 + v, ok ? 16 : 0);
    }
    asm volatile("cp.async.commit_group;" ::: "memory");
}

__global__ __launch_bounds__(256, 1) void k_encode_mma(const float* __restrict__ be) {
    extern __shared__ char dsraw[];
    char* dsm = (char*)(((uintptr_t)dsraw + 1023) & ~(uintptr_t)1023);
    uint32_t s_base = (uint32_t)__cvta_generic_to_shared(dsm);
    __shared__ float bias[216];

    int tid = threadIdx.x;
    int wid = tid >> 5, lane = tid & 31;
    int wm = wid & 1, wn = wid >> 1;     // m-warp (64 rows), n-group (7 subtiles)
    int b = blockIdx.x;
    int d = b >> 3, h0 = (b & 7) << 2;

    for (int i = tid; i < 216; i += 256) bias[i] = be[i];

    // per-lane ldmatrix address components
    int ar   = wm * 64 + (lane & 15);    // A tile row (m-tiles at +0,+16,+32,+48)
    int akh  = lane >> 4;                // A k-half
    int axor = ar & 7;                   // invariant across +16 m-tiles
    int nr   = lane & 7;                 // B row within n8 subtile
    int bkh  = (lane >> 3) & 1;          // B k-half
    int tsel = lane >> 4;                // B subtile-within-pair
    uint32_t bpair0 = A_TILE + (uint32_t)(wn * 7 + tsel) * 1024 + nr * 128;
    uint32_t b6base = A_TILE + (uint32_t)(wn * 7 + 6) * 1024 + nr * 128;

    float acc[112];                      // [subtile j(7)][mtile(4)][4]
#pragma unroll
    for (int i = 0; i < 112; ++i) acc[i] = 0.f;

    build_stage(s_base, 0, tid, d, h0);
    asm volatile("cp.async.wait_group 0;" ::: "memory");
    __syncthreads();

    for (int t = 0; t < 27; ++t) {
        int s = t & 1;
        if (t + 1 < 27) build_stage(s_base + (s ^ 1) * STG_SZ, t + 1, tid, d, h0);

        uint32_t stage = s_base + s * STG_SZ;
        uint32_t abase = stage + ar * 128;
#pragma unroll
        for (int ks = 0; ks < 4; ++ks) {
            uint32_t a[4][4];
            uint32_t aaddr = abase + ((((ks << 1) | akh) ^ axor) << 4);
            ldsm4(a[0], aaddr);
            ldsm4(a[1], aaddr + 16 * 128);
            ldsm4(a[2], aaddr + 32 * 128);
            ldsm4(a[3], aaddr + 48 * 128);

            uint32_t bswz = (((ks << 1) | bkh) ^ nr) << 4;
            uint32_t bp[3][4], b6[2];
#pragma unroll
            for (int jp = 0; jp < 3; ++jp)
                ldsm4(bp[jp], stage + bpair0 + jp * 2048 + bswz);
            ldsm2(b6, stage + b6base + bswz);

#pragma unroll
            for (int jp = 0; jp < 3; ++jp) {
#pragma unroll
                for (int mt = 0; mt < 4; ++mt) {
                    mma16816(&acc[(2 * jp) * 16 + mt * 4], a[mt], bp[jp]);
                    mma16816(&acc[(2 * jp + 1) * 16 + mt * 4], a[mt], bp[jp] + 2);
                }
            }
#pragma unroll
            for (int mt = 0; mt < 4; ++mt)
                mma16816(&acc[96 + mt * 4], a[mt], b6);
        }
        if (t + 1 < 27) asm volatile("cp.async.wait_group 0;" ::: "memory");
        __syncthreads();
    }

    // epilogue: c-frag -> g_w2 voxel-major [v][216] with bias, 8B v2 stores.
    int g = lane >> 2, tq = lane & 3;
    int vbase = d * 1024 + h0 * 32;
#pragma unroll
    for (int j = 0; j < 7; ++j) {
        if (wn == 3 && j == 6) break;     // subtile 27 is pad
        int c0 = (wn * 7 + j) * 8 + 2 * tq;
        float b0v = bias[c0], b1v = bias[c0 + 1];
#pragma unroll
        for (int mt = 0; mt < 4; ++mt) {
            int r = wm * 64 + mt * 16 + g;
            const float* cp = &acc[j * 16 + mt * 4];
            *(float2*)&g_w2[(u64)(vbase + r) * 216 + c0] =
                make_float2(cp[0] + b0v, cp[1] + b1v);
            *(float2*)&g_w2[(u64)(vbase + r + 8) * 216 + c0] =
                make_float2(cp[2] + b0v, cp[3] + b1v);
        }
    }
}

// ---------------------------------------------------------------------------
// Kernel 3: fused pixelshuffle + softmax(27) + factored reassembly.
// off-fast lane map (LDS broadcast on tap reads).  Outputs staged through
// smem (reusing the ps slab) and stored as 128 x 256B CONTIGUOUS rows.
// obuf rows padded to 68 floats (272B, 16B-aligned) — r9's 65-float pad made
// odd-row float4 reads misaligned (the crash).
// ---------------------------------------------------------------------------
#define OPAD 68
__global__ __launch_bounds__(256) void k_reassemble(float* __restrict__ out) {
    extern __shared__ char rsm[];
    u64*   ps   = (u64*)rsm;                      // 16*306 u64 (39168 B)
    float* obuf = (float*)rsm;                    // reused post-compute: 128*68*4 B

    int tid = threadIdx.x;
    int h = blockIdx.x, d = blockIdx.y;
    int off = tid & 7;                            // pd*4 + qh*2 + rw
    int w = tid >> 3;                             // 0..31
    int pd = off >> 2, qh = (off >> 1) & 1, rw = off & 1;
    int vbase = d * 1024 + h * 32;

    // projected-patch slab (replicate padding)
    for (int i = tid; i < 16 * 306; i += 256) {
        int pp = i / 306; int r = i - pp * 306;
        int kd = r / 102; int r2 = r - kd * 102;
        int kh = r2 / 34; int ii = r2 - kh * 34;
        int dd = min(max(d + kd - 1, 0), 31);
        int hh = min(max(h + kh - 1, 0), 31);
        int ww = min(max(ii - 1, 0), 31);
        ps[i] = g_p2[pp * N3 + dd * 1024 + hh * 32 + ww];
    }
    __syncthreads();

    // softmax over 27 taps: logits at g_w2[v][k*8 + off]
    const float* w2v = &g_w2[(u64)(vbase + w) * 216];
    float sw[27];
    float m = -1e30f;
#pragma unroll
    for (int k = 0; k < 27; ++k) {
        float v = w2v[k * 8 + off];
        sw[k] = v;
        m = fmaxf(m, v);
    }
    float s = 0.f;
#pragma unroll
    for (int k = 0; k < 27; ++k) { sw[k] = __expf(sw[k] - m); s += sw[k]; }
    float inv = 1.f / s;
#pragma unroll
    for (int k = 0; k < 27; ++k) sw[k] *= inv;

    u64 acc[16];
#pragma unroll
    for (int p = 0; p < 16; ++p) acc[p] = 0ull;
#pragma unroll
    for (int kd = 0; kd < 3; ++kd)
#pragma unroll
        for (int kh = 0; kh < 3; ++kh)
#pragma unroll
            for (int kw = 0; kw < 3; ++kw) {
                float sv = sw[(kd * 3 + kh) * 3 + kw];
                u64 sd = pk2(sv, sv);
                int base = kd * 102 + kh * 34 + w + kw;
#pragma unroll
                for (int p = 0; p < 16; ++p)
                    acc[p] = ffma2(sd, ps[p * 306 + base], acc[p]);
            }
    __syncthreads();   // everyone done reading ps; safe to overwrite with obuf

    // stage outputs: row = ch*4 + pd*2 + qh (128 rows), col = 2w+rw (64 cols)
    int rowbase = pd * 2 + qh;
    int col = 2 * w + rw;
#pragma unroll
    for (int p = 0; p < 16; ++p) {
        float a, bb; upk2(acc[p], a, bb);
        obuf[((2 * p) * 4 + rowbase) * OPAD + col]     = a;
        obuf[((2 * p + 1) * 4 + rowbase) * OPAD + col] = bb;
    }
    __syncthreads();

    // coalesced stores: 128 rows x 256B contiguous
    int d2b = 2 * d, h2b = 2 * h;
    for (int i = tid; i < 2048; i += 256) {      // i indexes float4
        int row = i >> 4, c4 = (i & 15) << 2;
        int ch = row >> 2, pdq = row & 3;
        float4 v = *(float4*)&obuf[row * OPAD + c4];
        *(float4*)&out[(u64)ch * NF + (d2b + (pdq >> 1)) * 4096 +
                       (h2b + (pdq & 1)) * 64 + c4] = v;
    }
}

// ---------------------------------------------------------------------------
extern "C" void kernel_launch(void* const* d_in, const int* in_sizes, int n_in,
                              void* d_out, int out_size) {
    const float* x  = (const float*)d_in[0];
    const float* wc = (const float*)d_in[1];
    const float* bc = (const float*)d_in[2];
    const float* we = (const float*)d_in[3];
    const float* be = (const float*)d_in[4];
    const float* wp = (const float*)d_in[5];
    float* out = (float*)d_out;

    const int enc_smem = 2 * STG_SZ + 1024;   // 91136
    const int rea_smem = 16 * 306 * 8;        // 39168 (obuf 34816 fits inside)
    static int smem_set = 0;
    if (!smem_set) {
        cudaFuncSetAttribute(k_encode_mma, cudaFuncAttributeMaxDynamicSharedMemorySize,
                             enc_smem);
        cudaFuncSetAttribute(k_reassemble, cudaFuncAttributeMaxDynamicSharedMemorySize,
                             rea_smem);
        smem_set = 1;
    }

    k_front<<<1586, 256>>>(x, wc, bc, wp, we);
    k_encode_mma<<<256, 256, enc_smem>>>(be);
    k_reassemble<<<dim3(32, 32), 256, rea_smem>>>(out);
}

// round 11
// speedup vs baseline: 4.7520x; 1.0216x over previous
#include <cuda_runtime.h>
#include <cuda_fp16.h>
#include <stdint.h>

// CARAFE3d: B=1, C=64, D=H=W=32, c_mid=64, s=2, k=3, out_ch=32
#define N3 32768      // 32^3 coarse voxels
#define NF 262144     // 64^3 fine voxels

typedef unsigned long long u64;

// ---------------- global scratch ----------------
__device__ __align__(16) __half g_xf[N3 * 64];         // compressed feats fp16, [v][c]
__device__ __align__(16) __half g_wf[27 * 224 * 64];   // weights fp16 [t][o pad224][c], pre-swizzled
__device__ float g_w2[N3 * 216];                       // encode output, voxel-major [v][ch]
__device__ u64   g_p2[16 * N3];                        // projected x, oc-pairs

// ---------------- helpers ----------------
__device__ __forceinline__ u64 pk2(float lo, float hi) {
    u64 r; asm("mov.b64 %0, {%1, %2};" : "=l"(r) : "f"(lo), "f"(hi)); return r;
}
__device__ __forceinline__ void upk2(u64 v, float& lo, float& hi) {
    asm("mov.b64 {%0, %1}, %2;" : "=f"(lo), "=f"(hi) : "l"(v));
}
__device__ __forceinline__ u64 ffma2(u64 a, u64 b, u64 c) {
    u64 d; asm("fma.rn.f32x2 %0, %1, %2, %3;" : "=l"(d) : "l"(a), "l"(b), "l"(c));
    return d;
}
__device__ __forceinline__ unsigned hfpk(float lo, float hi) {  // mem order: lo first
    unsigned r; asm("cvt.rn.f16x2.f32 %0, %1, %2;" : "=r"(r) : "f"(hi), "f"(lo));
    return r;
}
__device__ __forceinline__ void cp16(uint32_t dst, const void* src) {
    asm volatile("cp.async.ca.shared.global [%0], [%1], 16;" :: "r"(dst), "l"(src));
}
// zero-fill variant: src-size 0 -> writes 16B of zeros, reads nothing
__device__ __forceinline__ void cp16z(uint32_t dst, const void* src, int srcsz) {
    asm volatile("cp.async.ca.shared.global [%0], [%1], 16, %2;"
                 :: "r"(dst), "l"(src), "r"(srcsz));
}
__device__ __forceinline__ void ldsm4(uint32_t* r, uint32_t addr) {
    asm volatile("ldmatrix.sync.aligned.m8n8.x4.shared.b16 {%0,%1,%2,%3}, [%4];"
                 : "=r"(r[0]), "=r"(r[1]), "=r"(r[2]), "=r"(r[3]) : "r"(addr));
}
__device__ __forceinline__ void ldsm2(uint32_t* r, uint32_t addr) {
    asm volatile("ldmatrix.sync.aligned.m8n8.x2.shared.b16 {%0,%1}, [%2];"
                 : "=r"(r[0]), "=r"(r[1]) : "r"(addr));
}
__device__ __forceinline__ void mma16816(float* c, const uint32_t* a, const uint32_t* b) {
    asm volatile("mma.sync.aligned.m16n8k16.row.col.f32.f16.f16.f32 "
                 "{%0,%1,%2,%3}, {%4,%5,%6,%7}, {%8,%9}, {%0,%1,%2,%3};"
                 : "+f"(c[0]), "+f"(c[1]), "+f"(c[2]), "+f"(c[3])
                 : "r"(a[0]), "r"(a[1]), "r"(a[2]), "r"(a[3]), "r"(b[0]), "r"(b[1]));
}

// ---------------------------------------------------------------------------
// Kernel 1: MERGED front.
//  blocks [0,256):     compress+proj, TWO THREADS PER VOXEL (sub = tid&1
//                      owns half the outputs) -> 65K threads, ~half the regs
//  blocks [256,1714):  encode-weight prep -> [t][o pad224][c] fp16, swizzled
// ---------------------------------------------------------------------------
__global__ __launch_bounds__(256) void k_front(const float* __restrict__ x,
                                               const float* __restrict__ Wc,
                                               const float* __restrict__ bc,
                                               const float* __restrict__ Wp,
                                               const float* __restrict__ We) {
    if (blockIdx.x >= 256) {
        int id = (blockIdx.x - 256) * 256 + threadIdx.x;   // 27*216*64 = 373248
        int t = id / 13824;
        int r = id - t * 13824;
        int o = r >> 6, c = r & 63;
        float v = We[o * 1728 + c * 27 + t];
        int ci = c >> 3, j = c & 7;
        int dst = t * 14336 + o * 64 + ((ci ^ (o & 7)) << 3) + j;
        g_wf[dst] = __float2half(v);
        return;
    }

    __shared__ __align__(16) float Ws[64 * 64];   // compress [c][cm]
    __shared__ __align__(16) float Ps[64 * 32];   // proj     [c][oc]
    __shared__ float bs[64];
    int tid = threadIdx.x;
    for (int i = tid; i < 4096; i += 256) {
        int c = i >> 6, cm = i & 63;
        Ws[i] = Wc[cm * 64 + c];
    }
    for (int i = tid; i < 2048; i += 256) {
        int c = i >> 5, oc = i & 31;
        Ps[i] = Wp[oc * 64 + c];
    }
    if (tid < 64) bs[tid] = bc[tid];
    __syncthreads();

    int v = blockIdx.x * 128 + (tid >> 1);
    int sub = tid & 1;                    // output half this thread owns
    const u64* ws64 = (const u64*)Ws;     // 32 u64 per c-row
    const u64* ps64 = (const u64*)Ps;     // 16 u64 per c-row
    u64 acc[16], pacc[8];
#pragma unroll
    for (int p = 0; p < 16; ++p) {
        int cm = sub * 32 + 2 * p;
        acc[p] = pk2(bs[cm], bs[cm + 1]);
    }
#pragma unroll
    for (int p = 0; p < 8; ++p) pacc[p] = 0ull;

#pragma unroll 4
    for (int c = 0; c < 64; ++c) {
        float xv = x[c * N3 + v];
        u64 xd = pk2(xv, xv);
        const u64* wr = &ws64[c * 32 + sub * 16];
        const u64* pr = &ps64[c * 16 + sub * 8];
#pragma unroll
        for (int p = 0; p < 16; ++p) acc[p] = ffma2(xd, wr[p], acc[p]);
#pragma unroll
        for (int p = 0; p < 8; ++p) pacc[p] = ffma2(xd, pr[p], pacc[p]);
    }
#pragma unroll
    for (int p = 0; p < 8; ++p) g_p2[(sub * 8 + p) * N3 + v] = pacc[p];

    float vals[32];
#pragma unroll
    for (int p = 0; p < 16; ++p) upk2(acc[p], vals[2 * p], vals[2 * p + 1]);
    uint4* xf4 = (uint4*)g_xf;
#pragma unroll
    for (int i = 0; i < 4; ++i) {
        unsigned hw[4];
#pragma unroll
        for (int j = 0; j < 4; ++j)
            hw[j] = hfpk(vals[i * 8 + 2 * j], vals[i * 8 + 2 * j + 1]);
        xf4[v * 8 + sub * 4 + i] = make_uint4(hw[0], hw[1], hw[2], hw[3]);
    }
}

// ---------------------------------------------------------------------------
// Kernel 2: encode conv as single-pass fp16 mma.sync GEMM, 3-STAGE pipeline.
// CTA: M=128 voxels, N=216(+8 pad), K = 27 taps x 64c.  256 threads, 8 warps
// in 2(m) x 4(n): warp tile = m64 x n56.  Stage build fully cp.async; with
// 3 stages + wait_group 1 each transfer gets ~2 compute periods to land.
// ---------------------------------------------------------------------------
#define A_TILE 16384                 // 128 rows x 128 B
#define B_TILE 28672                 // 224 rows x 128 B
#define STG_SZ 45056                 // A then B

__device__ __forceinline__ void build_stage(uint32_t stage, int t, int tid,
                                            int d, int h0) {
    const char* srcB = (const char*)g_wf + t * B_TILE;
    for (int i = tid; i < 1792; i += 256)
        cp16(stage + A_TILE + i * 16, srcB + i * 16);
    int kd = t / 9; int rr = t - kd * 9; int kh = rr / 3; int kw = rr - kh * 3;
    const uint4* xf4 = (const uint4*)g_xf;
#pragma unroll
    for (int it = 0; it < 4; ++it) {
        int idx = tid + it * 256;            // 0..1023: row m (7b) x chunk ci (3b)
        int m = idx >> 3, ci = idx & 7;
        int hr = m >> 5, w = m & 31;
        int dd = d + kd - 1, hh = h0 + hr + kh - 1, ww = w + kw - 1;
        bool ok = (unsigned)dd < 32u && (unsigned)hh < 32u && (unsigned)ww < 32u;
        int v = ok ? (dd * 1024 + hh * 32 + ww) * 8 + ci : 0;
        uint32_t dst = stage + m * 128 + ((ci ^ (m & 7)) << 4);
        cp16z(dst, xf4 + v, ok ? 16 : 0);
    }
    asm volatile("cp.async.commit_group;" ::: "memory");
}

__global__ __launch_bounds__(256, 1) void k_encode_mma(const float* __restrict__ be) {
    extern __shared__ char dsraw[];
    char* dsm = (char*)(((uintptr_t)dsraw + 1023) & ~(uintptr_t)1023);
    uint32_t s_base = (uint32_t)__cvta_generic_to_shared(dsm);
    __shared__ float bias[216];

    int tid = threadIdx.x;
    int wid = tid >> 5, lane = tid & 31;
    int wm = wid & 1, wn = wid >> 1;     // m-warp (64 rows), n-group (7 subtiles)
    int b = blockIdx.x;
    int d = b >> 3, h0 = (b & 7) << 2;

    for (int i = tid; i < 216; i += 256) bias[i] = be[i];

    // per-lane ldmatrix address components
    int ar   = wm * 64 + (lane & 15);    // A tile row (m-tiles at +0,+16,+32,+48)
    int akh  = lane >> 4;                // A k-half
    int axor = ar & 7;                   // invariant across +16 m-tiles
    int nr   = lane & 7;                 // B row within n8 subtile
    int bkh  = (lane >> 3) & 1;          // B k-half
    int tsel = lane >> 4;                // B subtile-within-pair
    uint32_t bpair0 = A_TILE + (uint32_t)(wn * 7 + tsel) * 1024 + nr * 128;
    uint32_t b6base = A_TILE + (uint32_t)(wn * 7 + 6) * 1024 + nr * 128;

    float acc[112];                      // [subtile j(7)][mtile(4)][4]
#pragma unroll
    for (int i = 0; i < 112; ++i) acc[i] = 0.f;

    build_stage(s_base, 0, tid, d, h0);
    build_stage(s_base + STG_SZ, 1, tid, d, h0);
    asm volatile("cp.async.wait_group 1;" ::: "memory");   // stage 0 ready
    __syncthreads();

    for (int t = 0; t < 27; ++t) {
        int s = t % 3;
        uint32_t stage = s_base + s * STG_SZ;
        uint32_t abase = stage + ar * 128;
#pragma unroll
        for (int ks = 0; ks < 4; ++ks) {
            uint32_t a[4][4];
            uint32_t aaddr = abase + ((((ks << 1) | akh) ^ axor) << 4);
            ldsm4(a[0], aaddr);
            ldsm4(a[1], aaddr + 16 * 128);
            ldsm4(a[2], aaddr + 32 * 128);
            ldsm4(a[3], aaddr + 48 * 128);

            uint32_t bswz = (((ks << 1) | bkh) ^ nr) << 4;
            uint32_t bp[3][4], b6[2];
#pragma unroll
            for (int jp = 0; jp < 3; ++jp)
                ldsm4(bp[jp], stage + bpair0 + jp * 2048 + bswz);
            ldsm2(b6, stage + b6base + bswz);

#pragma unroll
            for (int jp = 0; jp < 3; ++jp) {
#pragma unroll
                for (int mt = 0; mt < 4; ++mt) {
                    mma16816(&acc[(2 * jp) * 16 + mt * 4], a[mt], bp[jp]);
                    mma16816(&acc[(2 * jp + 1) * 16 + mt * 4], a[mt], bp[jp] + 2);
                }
            }
#pragma unroll
            for (int mt = 0; mt < 4; ++mt)
                mma16816(&acc[96 + mt * 4], a[mt], b6);
        }
        if (t + 2 < 27) {
            build_stage(s_base + ((t + 2) % 3) * STG_SZ, t + 2, tid, d, h0);
            asm volatile("cp.async.wait_group 1;" ::: "memory");   // t+1 ready
        } else if (t + 1 < 27) {
            asm volatile("cp.async.wait_group 0;" ::: "memory");
        }
        __syncthreads();
    }

    // epilogue: c-frag -> g_w2 voxel-major [v][216] with bias, 8B v2 stores.
    int g = lane >> 2, tq = lane & 3;
    int vbase = d * 1024 + h0 * 32;
#pragma unroll
    for (int j = 0; j < 7; ++j) {
        if (wn == 3 && j == 6) break;     // subtile 27 is pad
        int c0 = (wn * 7 + j) * 8 + 2 * tq;
        float b0v = bias[c0], b1v = bias[c0 + 1];
#pragma unroll
        for (int mt = 0; mt < 4; ++mt) {
            int r = wm * 64 + mt * 16 + g;
            const float* cp = &acc[j * 16 + mt * 4];
            *(float2*)&g_w2[(u64)(vbase + r) * 216 + c0] =
                make_float2(cp[0] + b0v, cp[1] + b1v);
            *(float2*)&g_w2[(u64)(vbase + r + 8) * 216 + c0] =
                make_float2(cp[2] + b0v, cp[3] + b1v);
        }
    }
}

// ---------------------------------------------------------------------------
// Kernel 3: fused pixelshuffle + softmax(27) + factored reassembly.
// off-fast lane map; outputs staged in smem, stored as 256B-contiguous rows.
// ---------------------------------------------------------------------------
#define OPAD 68
__global__ __launch_bounds__(256) void k_reassemble(float* __restrict__ out) {
    extern __shared__ char rsm[];
    u64*   ps   = (u64*)rsm;                      // 16*306 u64 (39168 B)
    float* obuf = (float*)rsm;                    // reused post-compute: 128*68*4 B

    int tid = threadIdx.x;
    int h = blockIdx.x, d = blockIdx.y;
    int off = tid & 7;                            // pd*4 + qh*2 + rw
    int w = tid >> 3;                             // 0..31
    int pd = off >> 2, qh = (off >> 1) & 1, rw = off & 1;
    int vbase = d * 1024 + h * 32;

    // projected-patch slab (replicate padding)
    for (int i = tid; i < 16 * 306; i += 256) {
        int pp = i / 306; int r = i - pp * 306;
        int kd = r / 102; int r2 = r - kd * 102;
        int kh = r2 / 34; int ii = r2 - kh * 34;
        int dd = min(max(d + kd - 1, 0), 31);
        int hh = min(max(h + kh - 1, 0), 31);
        int ww = min(max(ii - 1, 0), 31);
        ps[i] = g_p2[pp * N3 + dd * 1024 + hh * 32 + ww];
    }
    __syncthreads();

    // softmax over 27 taps: logits at g_w2[v][k*8 + off]
    const float* w2v = &g_w2[(u64)(vbase + w) * 216];
    float sw[27];
    float m = -1e30f;
#pragma unroll
    for (int k = 0; k < 27; ++k) {
        float v = w2v[k * 8 + off];
        sw[k] = v;
        m = fmaxf(m, v);
    }
    float s = 0.f;
#pragma unroll
    for (int k = 0; k < 27; ++k) { sw[k] = __expf(sw[k] - m); s += sw[k]; }
    float inv = 1.f / s;
#pragma unroll
    for (int k = 0; k < 27; ++k) sw[k] *= inv;

    u64 acc[16];
#pragma unroll
    for (int p = 0; p < 16; ++p) acc[p] = 0ull;
#pragma unroll
    for (int kd = 0; kd < 3; ++kd)
#pragma unroll
        for (int kh = 0; kh < 3; ++kh)
#pragma unroll
            for (int kw = 0; kw < 3; ++kw) {
                float sv = sw[(kd * 3 + kh) * 3 + kw];
                u64 sd = pk2(sv, sv);
                int base = kd * 102 + kh * 34 + w + kw;
#pragma unroll
                for (int p = 0; p < 16; ++p)
                    acc[p] = ffma2(sd, ps[p * 306 + base], acc[p]);
            }
    __syncthreads();   // everyone done reading ps; safe to overwrite with obuf

    // stage outputs: row = ch*4 + pd*2 + qh (128 rows), col = 2w+rw (64 cols)
    int rowbase = pd * 2 + qh;
    int col = 2 * w + rw;
#pragma unroll
    for (int p = 0; p < 16; ++p) {
        float a, bb; upk2(acc[p], a, bb);
        obuf[((2 * p) * 4 + rowbase) * OPAD + col]     = a;
        obuf[((2 * p + 1) * 4 + rowbase) * OPAD + col] = bb;
    }
    __syncthreads();

    // coalesced stores: 128 rows x 256B contiguous
    int d2b = 2 * d, h2b = 2 * h;
    for (int i = tid; i < 2048; i += 256) {      // i indexes float4
        int row = i >> 4, c4 = (i & 15) << 2;
        int ch = row >> 2, pdq = row & 3;
        float4 v = *(float4*)&obuf[row * OPAD + c4];
        *(float4*)&out[(u64)ch * NF + (d2b + (pdq >> 1)) * 4096 +
                       (h2b + (pdq & 1)) * 64 + c4] = v;
    }
}

// ---------------------------------------------------------------------------
extern "C" void kernel_launch(void* const* d_in, const int* in_sizes, int n_in,
                              void* d_out, int out_size) {
    const float* x  = (const float*)d_in[0];
    const float* wc = (const float*)d_in[1];
    const float* bc = (const float*)d_in[2];
    const float* we = (const float*)d_in[3];
    const float* be = (const float*)d_in[4];
    const float* wp = (const float*)d_in[5];
    float* out = (float*)d_out;

    const int enc_smem = 3 * STG_SZ + 1024;   // 136192
    const int rea_smem = 16 * 306 * 8;        // 39168 (obuf 34816 fits inside)
    static int smem_set = 0;
    if (!smem_set) {
        cudaFuncSetAttribute(k_encode_mma, cudaFuncAttributeMaxDynamicSharedMemorySize,
                             enc_smem);
        cudaFuncSetAttribute(k_reassemble, cudaFuncAttributeMaxDynamicSharedMemorySize,
                             rea_smem);
        smem_set = 1;
    }

    k_front<<<1714, 256>>>(x, wc, bc, wp, we);
    k_encode_mma<<<256, 256, enc_smem>>>(be);
    k_reassemble<<<dim3(32, 32), 256, rea_smem>>>(out);
}

// round 12
// speedup vs baseline: 4.8090x; 1.0120x over previous
#include <cuda_runtime.h>
#include <cuda_fp16.h>
#include <stdint.h>

// CARAFE3d: B=1, C=64, D=H=W=32, c_mid=64, s=2, k=3, out_ch=32
#define N3 32768      // 32^3 coarse voxels
#define NF 262144     // 64^3 fine voxels

typedef unsigned long long u64;

// ---------------- global scratch ----------------
__device__ __align__(16) __half g_xf[N3 * 64];         // compressed feats fp16, [v][c]
__device__ __align__(16) __half g_wf[27 * 224 * 64];   // weights fp16 [t][o pad224][c], pre-swizzled
__device__ float g_w2[N3 * 216];                       // encode output, voxel-major [v][ch]
__device__ u64   g_p2[16 * N3];                        // projected x, oc-pairs

// ---------------- helpers ----------------
__device__ __forceinline__ u64 pk2(float lo, float hi) {
    u64 r; asm("mov.b64 %0, {%1, %2};" : "=l"(r) : "f"(lo), "f"(hi)); return r;
}
__device__ __forceinline__ void upk2(u64 v, float& lo, float& hi) {
    asm("mov.b64 {%0, %1}, %2;" : "=f"(lo), "=f"(hi) : "l"(v));
}
__device__ __forceinline__ u64 ffma2(u64 a, u64 b, u64 c) {
    u64 d; asm("fma.rn.f32x2 %0, %1, %2, %3;" : "=l"(d) : "l"(a), "l"(b), "l"(c));
    return d;
}
__device__ __forceinline__ unsigned hfpk(float lo, float hi) {  // mem order: lo first
    unsigned r; asm("cvt.rn.f16x2.f32 %0, %1, %2;" : "=r"(r) : "f"(hi), "f"(lo));
    return r;
}
__device__ __forceinline__ void cp16(uint32_t dst, const void* src) {
    asm volatile("cp.async.ca.shared.global [%0], [%1], 16;" :: "r"(dst), "l"(src));
}
// zero-fill variant: src-size 0 -> writes 16B of zeros, reads nothing
__device__ __forceinline__ void cp16z(uint32_t dst, const void* src, int srcsz) {
    asm volatile("cp.async.ca.shared.global [%0], [%1], 16, %2;"
                 :: "r"(dst), "l"(src), "r"(srcsz));
}
__device__ __forceinline__ void ldsm4(uint32_t* r, uint32_t addr) {
    asm volatile("ldmatrix.sync.aligned.m8n8.x4.shared.b16 {%0,%1,%2,%3}, [%4];"
                 : "=r"(r[0]), "=r"(r[1]), "=r"(r[2]), "=r"(r[3]) : "r"(addr));
}
__device__ __forceinline__ void ldsm2(uint32_t* r, uint32_t addr) {
    asm volatile("ldmatrix.sync.aligned.m8n8.x2.shared.b16 {%0,%1}, [%2];"
                 : "=r"(r[0]), "=r"(r[1]) : "r"(addr));
}
__device__ __forceinline__ void mma16816(float* c, const uint32_t* a, const uint32_t* b) {
    asm volatile("mma.sync.aligned.m16n8k16.row.col.f32.f16.f16.f32 "
                 "{%0,%1,%2,%3}, {%4,%5,%6,%7}, {%8,%9}, {%0,%1,%2,%3};"
                 : "+f"(c[0]), "+f"(c[1]), "+f"(c[2]), "+f"(c[3])
                 : "r"(a[0]), "r"(a[1]), "r"(a[2]), "r"(a[3]), "r"(b[0]), "r"(b[1]));
}

// ---------------------------------------------------------------------------
// Kernel 1: MERGED front.
//  blocks [0,256):     compress+proj, 2 threads/voxel.  Weights packed in ONE
//                      interleaved slab: row c = 48 u64 (384B); sub-halves at
//                      +0B / +192B (bank distance 16 -> conflict-free), read
//                      as 12 LDS.128 per c (r11: 24 bank-conflicted LDS.64).
//  blocks [256,1714):  encode-weight prep -> [t][o pad224][c] fp16, swizzled
// ---------------------------------------------------------------------------
__global__ __launch_bounds__(256) void k_front(const float* __restrict__ x,
                                               const float* __restrict__ Wc,
                                               const float* __restrict__ bc,
                                               const float* __restrict__ Wp,
                                               const float* __restrict__ We) {
    if (blockIdx.x >= 256) {
        int id = (blockIdx.x - 256) * 256 + threadIdx.x;   // 27*216*64 = 373248
        int t = id / 13824;
        int r = id - t * 13824;
        int o = r >> 6, c = r & 63;
        float v = We[o * 1728 + c * 27 + t];
        int ci = c >> 3, j = c & 7;
        int dst = t * 14336 + o * 64 + ((ci ^ (o & 7)) << 3) + j;
        g_wf[dst] = __float2half(v);
        return;
    }

    __shared__ __align__(16) u64 WB[64 * 48];  // [c][sub(24 each)]: 16 cmp + 8 proj
    __shared__ float bs[64];
    int tid = threadIdx.x;
    // fill: WB[c][sub*24 + p], p<16 -> compress pair (sub*32+2p), p>=16 -> proj
    for (int i = tid; i < 3072; i += 256) {
        int c = i / 48, j = i - c * 48;
        int sub = j / 24, p = j - sub * 24;
        u64 w;
        if (p < 16) {
            int cm = sub * 32 + 2 * p;
            w = pk2(Wc[cm * 64 + c], Wc[(cm + 1) * 64 + c]);
        } else {
            int oc = sub * 16 + 2 * (p - 16);
            w = pk2(Wp[oc * 64 + c], Wp[(oc + 1) * 64 + c]);
        }
        WB[i] = w;
    }
    if (tid < 64) bs[tid] = bc[tid];
    __syncthreads();

    int v = blockIdx.x * 128 + (tid >> 1);
    int sub = tid & 1;                    // output half this thread owns
    u64 acc[24];                          // [0..15] compress, [16..23] proj
#pragma unroll
    for (int p = 0; p < 16; ++p) {
        int cm = sub * 32 + 2 * p;
        acc[p] = pk2(bs[cm], bs[cm + 1]);
    }
#pragma unroll
    for (int p = 16; p < 24; ++p) acc[p] = 0ull;

    const ulonglong2* wrow = (const ulonglong2*)&WB[sub * 24];
#pragma unroll 4
    for (int c = 0; c < 64; ++c) {
        float xv = x[c * N3 + v];
        u64 xd = pk2(xv, xv);
        const ulonglong2* row = wrow + c * 24;   // 24 ull2 per c-row (48 u64)
#pragma unroll
        for (int q = 0; q < 12; ++q) {
            ulonglong2 t = row[q];
            acc[2 * q]     = ffma2(xd, t.x, acc[2 * q]);
            acc[2 * q + 1] = ffma2(xd, t.y, acc[2 * q + 1]);
        }
    }
#pragma unroll
    for (int q = 0; q < 8; ++q) g_p2[(sub * 8 + q) * N3 + v] = acc[16 + q];

    float vals[32];
#pragma unroll
    for (int p = 0; p < 16; ++p) upk2(acc[p], vals[2 * p], vals[2 * p + 1]);
    uint4* xf4 = (uint4*)g_xf;
#pragma unroll
    for (int i = 0; i < 4; ++i) {
        unsigned hw[4];
#pragma unroll
        for (int j = 0; j < 4; ++j)
            hw[j] = hfpk(vals[i * 8 + 2 * j], vals[i * 8 + 2 * j + 1]);
        xf4[v * 8 + sub * 4 + i] = make_uint4(hw[0], hw[1], hw[2], hw[3]);
    }
}

// ---------------------------------------------------------------------------
// Kernel 2: encode conv as single-pass fp16 mma.sync GEMM, 3-stage pipeline.
// CTA: M=128 voxels, N=216(+8 pad), K = 27 taps x 64c.  512 threads, 16 warps
// in 4(m) x 4(n): warp tile = m32 x n56 -> acc 56, ~105 regs, 4 warps/SMSP.
// ---------------------------------------------------------------------------
#define A_TILE 16384                 // 128 rows x 128 B
#define B_TILE 28672                 // 224 rows x 128 B
#define STG_SZ 45056                 // A then B

__device__ __forceinline__ void build_stage(uint32_t stage, int t, int tid,
                                            int d, int h0) {
    const char* srcB = (const char*)g_wf + t * B_TILE;
    for (int i = tid; i < 1792; i += 512)
        cp16(stage + A_TILE + i * 16, srcB + i * 16);
    int kd = t / 9; int rr = t - kd * 9; int kh = rr / 3; int kw = rr - kh * 3;
    const uint4* xf4 = (const uint4*)g_xf;
#pragma unroll
    for (int it = 0; it < 2; ++it) {
        int idx = tid + it * 512;            // 0..1023: row m (7b) x chunk ci (3b)
        int m = idx >> 3, ci = idx & 7;
        int hr = m >> 5, w = m & 31;
        int dd = d + kd - 1, hh = h0 + hr + kh - 1, ww = w + kw - 1;
        bool ok = (unsigned)dd < 32u && (unsigned)hh < 32u && (unsigned)ww < 32u;
        int v = ok ? (dd * 1024 + hh * 32 + ww) * 8 + ci : 0;
        uint32_t dst = stage + m * 128 + ((ci ^ (m & 7)) << 4);
        cp16z(dst, xf4 + v, ok ? 16 : 0);
    }
    asm volatile("cp.async.commit_group;" ::: "memory");
}

__global__ __launch_bounds__(512, 1) void k_encode_mma(const float* __restrict__ be) {
    extern __shared__ char dsraw[];
    char* dsm = (char*)(((uintptr_t)dsraw + 1023) & ~(uintptr_t)1023);
    uint32_t s_base = (uint32_t)__cvta_generic_to_shared(dsm);
    __shared__ float bias[216];

    int tid = threadIdx.x;
    int wid = tid >> 5, lane = tid & 31;
    int wm = wid & 3, wn = wid >> 2;     // m-warp (32 rows), n-group (7 subtiles)
    int b = blockIdx.x;
    int d = b >> 3, h0 = (b & 7) << 2;

    for (int i = tid; i < 216; i += 512) bias[i] = be[i];

    // per-lane ldmatrix address components
    int ar   = wm * 32 + (lane & 15);    // A tile row (m-tiles at +0,+16)
    int akh  = lane >> 4;                // A k-half
    int axor = ar & 7;                   // invariant across +16 m-tiles
    int nr   = lane & 7;                 // B row within n8 subtile
    int bkh  = (lane >> 3) & 1;          // B k-half
    int tsel = lane >> 4;                // B subtile-within-pair
    uint32_t bpair0 = A_TILE + (uint32_t)(wn * 7 + tsel) * 1024 + nr * 128;
    uint32_t b6base = A_TILE + (uint32_t)(wn * 7 + 6) * 1024 + nr * 128;

    float acc[56];                       // [subtile j(7)][mtile(2)][4]
#pragma unroll
    for (int i = 0; i < 56; ++i) acc[i] = 0.f;

    build_stage(s_base, 0, tid, d, h0);
    build_stage(s_base + STG_SZ, 1, tid, d, h0);
    asm volatile("cp.async.wait_group 1;" ::: "memory");   // stage 0 ready
    __syncthreads();

    for (int t = 0; t < 27; ++t) {
        int s = t % 3;
        uint32_t stage = s_base + s * STG_SZ;
        uint32_t abase = stage + ar * 128;
#pragma unroll
        for (int ks = 0; ks < 4; ++ks) {
            uint32_t a[2][4];
            uint32_t aaddr = abase + ((((ks << 1) | akh) ^ axor) << 4);
            ldsm4(a[0], aaddr);
            ldsm4(a[1], aaddr + 16 * 128);

            uint32_t bswz = (((ks << 1) | bkh) ^ nr) << 4;
            uint32_t bp[3][4], b6[2];
#pragma unroll
            for (int jp = 0; jp < 3; ++jp)
                ldsm4(bp[jp], stage + bpair0 + jp * 2048 + bswz);
            ldsm2(b6, stage + b6base + bswz);

#pragma unroll
            for (int jp = 0; jp < 3; ++jp) {
#pragma unroll
                for (int mt = 0; mt < 2; ++mt) {
                    mma16816(&acc[(2 * jp) * 8 + mt * 4], a[mt], bp[jp]);
                    mma16816(&acc[(2 * jp + 1) * 8 + mt * 4], a[mt], bp[jp] + 2);
                }
            }
#pragma unroll
            for (int mt = 0; mt < 2; ++mt)
                mma16816(&acc[48 + mt * 4], a[mt], b6);
        }
        if (t + 2 < 27) {
            build_stage(s_base + ((t + 2) % 3) * STG_SZ, t + 2, tid, d, h0);
            asm volatile("cp.async.wait_group 1;" ::: "memory");   // t+1 ready
        } else if (t + 1 < 27) {
            asm volatile("cp.async.wait_group 0;" ::: "memory");
        }
        __syncthreads();
    }

    // epilogue: c-frag -> g_w2 voxel-major [v][216] with bias, 8B v2 stores.
    int g = lane >> 2, tq = lane & 3;
    int vbase = d * 1024 + h0 * 32;
#pragma unroll
    for (int j = 0; j < 7; ++j) {
        if (wn == 3 && j == 6) break;     // subtile 27 is pad
        int c0 = (wn * 7 + j) * 8 + 2 * tq;
        float b0v = bias[c0], b1v = bias[c0 + 1];
#pragma unroll
        for (int mt = 0; mt < 2; ++mt) {
            int r = wm * 32 + mt * 16 + g;
            const float* cp = &acc[j * 8 + mt * 4];
            *(float2*)&g_w2[(u64)(vbase + r) * 216 + c0] =
                make_float2(cp[0] + b0v, cp[1] + b1v);
            *(float2*)&g_w2[(u64)(vbase + r + 8) * 216 + c0] =
                make_float2(cp[2] + b0v, cp[3] + b1v);
        }
    }
}

// ---------------------------------------------------------------------------
// Kernel 3: fused pixelshuffle + softmax(27) + factored reassembly.
// off-fast lane map; outputs staged in smem, stored as 256B-contiguous rows.
// ---------------------------------------------------------------------------
#define OPAD 68
__global__ __launch_bounds__(256) void k_reassemble(float* __restrict__ out) {
    extern __shared__ char rsm[];
    u64*   ps   = (u64*)rsm;                      // 16*306 u64 (39168 B)
    float* obuf = (float*)rsm;                    // reused post-compute: 128*68*4 B

    int tid = threadIdx.x;
    int h = blockIdx.x, d = blockIdx.y;
    int off = tid & 7;                            // pd*4 + qh*2 + rw
    int w = tid >> 3;                             // 0..31
    int pd = off >> 2, qh = (off >> 1) & 1, rw = off & 1;
    int vbase = d * 1024 + h * 32;

    // projected-patch slab (replicate padding)
    for (int i = tid; i < 16 * 306; i += 256) {
        int pp = i / 306; int r = i - pp * 306;
        int kd = r / 102; int r2 = r - kd * 102;
        int kh = r2 / 34; int ii = r2 - kh * 34;
        int dd = min(max(d + kd - 1, 0), 31);
        int hh = min(max(h + kh - 1, 0), 31);
        int ww = min(max(ii - 1, 0), 31);
        ps[i] = g_p2[pp * N3 + dd * 1024 + hh * 32 + ww];
    }
    __syncthreads();

    // softmax over 27 taps: logits at g_w2[v][k*8 + off]
    const float* w2v = &g_w2[(u64)(vbase + w) * 216];
    float sw[27];
    float m = -1e30f;
#pragma unroll
    for (int k = 0; k < 27; ++k) {
        float v = w2v[k * 8 + off];
        sw[k] = v;
        m = fmaxf(m, v);
    }
    float s = 0.f;
#pragma unroll
    for (int k = 0; k < 27; ++k) { sw[k] = __expf(sw[k] - m); s += sw[k]; }
    float inv = 1.f / s;
#pragma unroll
    for (int k = 0; k < 27; ++k) sw[k] *= inv;

    u64 acc[16];
#pragma unroll
    for (int p = 0; p < 16; ++p) acc[p] = 0ull;
#pragma unroll
    for (int kd = 0; kd < 3; ++kd)
#pragma unroll
        for (int kh = 0; kh < 3; ++kh)
#pragma unroll
            for (int kw = 0; kw < 3; ++kw) {
                float sv = sw[(kd * 3 + kh) * 3 + kw];
                u64 sd = pk2(sv, sv);
                int base = kd * 102 + kh * 34 + w + kw;
#pragma unroll
                for (int p = 0; p < 16; ++p)
                    acc[p] = ffma2(sd, ps[p * 306 + base], acc[p]);
            }
    __syncthreads();   // everyone done reading ps; safe to overwrite with obuf

    // stage outputs: row = ch*4 + pd*2 + qh (128 rows), col = 2w+rw (64 cols)
    int rowbase = pd * 2 + qh;
    int col = 2 * w + rw;
#pragma unroll
    for (int p = 0; p < 16; ++p) {
        float a, bb; upk2(acc[p], a, bb);
        obuf[((2 * p) * 4 + rowbase) * OPAD + col]     = a;
        obuf[((2 * p + 1) * 4 + rowbase) * OPAD + col] = bb;
    }
    __syncthreads();

    // coalesced stores: 128 rows x 256B contiguous
    int d2b = 2 * d, h2b = 2 * h;
    for (int i = tid; i < 2048; i += 256) {      // i indexes float4
        int row = i >> 4, c4 = (i & 15) << 2;
        int ch = row >> 2, pdq = row & 3;
        float4 v = *(float4*)&obuf[row * OPAD + c4];
        *(float4*)&out[(u64)ch * NF + (d2b + (pdq >> 1)) * 4096 +
                       (h2b + (pdq & 1)) * 64 + c4] = v;
    }
}

// ---------------------------------------------------------------------------
extern "C" void kernel_launch(void* const* d_in, const int* in_sizes, int n_in,
                              void* d_out, int out_size) {
    const float* x  = (const float*)d_in[0];
    const float* wc = (const float*)d_in[1];
    const float* bc = (const float*)d_in[2];
    const float* we = (const float*)d_in[3];
    const float* be = (const float*)d_in[4];
    const float* wp = (const float*)d_in[5];
    float* out = (float*)d_out;

    const int enc_smem = 3 * STG_SZ + 1024;   // 136192
    const int rea_smem = 16 * 306 * 8;        // 39168 (obuf 34816 fits inside)
    static int smem_set = 0;
    if (!smem_set) {
        cudaFuncSetAttribute(k_encode_mma, cudaFuncAttributeMaxDynamicSharedMemorySize,
                             enc_smem);
        cudaFuncSetAttribute(k_reassemble, cudaFuncAttributeMaxDynamicSharedMemorySize,
                             rea_smem);
        smem_set = 1;
    }

    k_front<<<1714, 256>>>(x, wc, bc, wp, we);
    k_encode_mma<<<256, 512, enc_smem>>>(be);
    k_reassemble<<<dim3(32, 32), 256, rea_smem>>>(out);
}